// round 12
// baseline (speedup 1.0000x reference)
#include <cuda_runtime.h>
#include <cuda_bf16.h>
#include <math.h>
#include <stdint.h>

#define NH    16
#define NKV   8
#define HD    128
#define CEMB  2048
#define BATCH 2
#define TSEQ  2048
#define MROWS (BATCH * TSEQ)
#define KVC   (NKV * HD)   // 1024

// ---------------- scratch ----------------------------------------------------
__device__ float g_qkv[MROWS * 4096];   // per row: q(2048) | k(1024) | v(1024)
__device__ float g_qn [MROWS * CEMB];
__device__ float g_kn [MROWS * KVC];
__device__ float g_ag [MROWS * NH];

__device__ __nv_bfloat16 g_x2   [MROWS * 2 * CEMB];
__device__ __nv_bfloat16 g_y2   [MROWS * 2 * CEMB];   // attention writes this directly
__device__ __nv_bfloat16 g_wqkvt[2 * 4096 * CEMB];
__device__ __nv_bfloat16 g_wpt  [2 * CEMB * CEMB];

// ---------------- helpers ----------------------------------------------------
__device__ __forceinline__ uint32_t smem_u32(const void* p) {
    uint32_t a;
    asm("{ .reg .u64 t; cvta.to.shared.u64 t, %1; cvt.u32.u64 %0, t; }" : "=r"(a) : "l"(p));
    return a;
}
#define CP_ASYNC16(dst, src) \
    asm volatile("cp.async.cg.shared.global [%0], [%1], 16;" :: "r"(dst), "l"(src))
#define CP_COMMIT() asm volatile("cp.async.commit_group;" ::: "memory")
#define CP_WAIT1()  asm volatile("cp.async.wait_group 1;" ::: "memory")

__device__ __forceinline__ void ldm_x4(uint32_t& r0, uint32_t& r1, uint32_t& r2, uint32_t& r3,
                                       uint32_t addr) {
    asm volatile("ldmatrix.sync.aligned.m8n8.x4.shared.b16 {%0,%1,%2,%3}, [%4];"
                 : "=r"(r0), "=r"(r1), "=r"(r2), "=r"(r3) : "r"(addr));
}
__device__ __forceinline__ void mma_bf16(float& d0, float& d1, float& d2, float& d3,
                                         uint32_t a0, uint32_t a1, uint32_t a2, uint32_t a3,
                                         uint32_t b0, uint32_t b1) {
    asm volatile("mma.sync.aligned.m16n8k16.row.col.f32.bf16.bf16.f32 "
                 "{%0,%1,%2,%3}, {%4,%5,%6,%7}, {%8,%9}, {%0,%1,%2,%3};"
                 : "+f"(d0), "+f"(d1), "+f"(d2), "+f"(d3)
                 : "r"(a0), "r"(a1), "r"(a2), "r"(a3), "r"(b0), "r"(b1));
}

// ---------------- packed fp32x2 + fast exp2 ----------------------------------
__device__ __forceinline__ uint64_t pk2(float lo, float hi) {
    float2 f = make_float2(lo, hi);
    return *reinterpret_cast<uint64_t*>(&f);
}
__device__ __forceinline__ float2 upk2(uint64_t u) {
    return *reinterpret_cast<float2*>(&u);
}
__device__ __forceinline__ uint64_t fma2(uint64_t a, uint64_t b, uint64_t c) {
    uint64_t d;
    asm("fma.rn.f32x2 %0, %1, %2, %3;" : "=l"(d) : "l"(a), "l"(b), "l"(c));
    return d;
}
__device__ __forceinline__ float ex2f(float x) {
    float y;
    asm("ex2.approx.f32 %0, %1;" : "=f"(y) : "f"(x));
    return y;
}

// ---------------- fused operand conversion (one launch) ----------------------
__global__ __launch_bounds__(256) void conv_all(
    const float* __restrict__ x,
    const float* __restrict__ wq, const float* __restrict__ wk,
    const float* __restrict__ wv, const float* __restrict__ wproj,
    __nv_bfloat16* __restrict__ x2,
    __nv_bfloat16* __restrict__ wqkvt, __nv_bfloat16* __restrict__ wpt)
{
    const int tid = threadIdx.x;
    if (blockIdx.x < 8192) {
        const int idx = (blockIdx.x * 256 + tid) * 4;
        const int row = idx >> 11;
        const int col = idx & 2047;
        float4 v = *(const float4*)(x + (size_t)row * CEMB + col);
        __nv_bfloat16 h0 = __float2bfloat16(v.x), h1 = __float2bfloat16(v.y);
        __nv_bfloat16 h2 = __float2bfloat16(v.z), h3 = __float2bfloat16(v.w);
        __nv_bfloat16 l0 = __float2bfloat16(v.x - __bfloat162float(h0));
        __nv_bfloat16 l1 = __float2bfloat16(v.y - __bfloat162float(h1));
        __nv_bfloat16 l2 = __float2bfloat16(v.z - __bfloat162float(h2));
        __nv_bfloat16 l3 = __float2bfloat16(v.w - __bfloat162float(h3));
        __nv_bfloat16* base = x2 + (size_t)row * 4096;
        *(__nv_bfloat162*)(base + col)            = __nv_bfloat162(h0, h1);
        *(__nv_bfloat162*)(base + col + 2)        = __nv_bfloat162(h2, h3);
        *(__nv_bfloat162*)(base + 2048 + col)     = __nv_bfloat162(l0, l1);
        *(__nv_bfloat162*)(base + 2048 + col + 2) = __nv_bfloat162(l2, l3);
        return;
    }
    __shared__ float tile[32][33];
    const int fidx = blockIdx.x - 8192;
    const int bx = fidx % 192;
    const int ky = fidx / 192;
    const float* w; __nv_bfloat16* wt;
    int N_src, hib, lob, n0;
    if (bx < 64)       { w = wq;    wt = wqkvt; N_src = 2048; hib = 0;    lob = 4096; n0 = bx * 32; }
    else if (bx < 96)  { w = wk;    wt = wqkvt; N_src = 1024; hib = 2048; lob = 6144; n0 = (bx - 64) * 32; }
    else if (bx < 128) { w = wv;    wt = wqkvt; N_src = 1024; hib = 3072; lob = 7168; n0 = (bx - 96) * 32; }
    else               { w = wproj; wt = wpt;   N_src = 2048; hib = 0;    lob = 2048; n0 = (bx - 128) * 32; }

    const int k0 = ky * 32;
    const int tx = tid & 31, ty = tid >> 5;
#pragma unroll
    for (int r = 0; r < 4; r++)
        tile[ty + 8 * r][tx] = w[(size_t)(k0 + ty + 8 * r) * N_src + n0 + tx];
    __syncthreads();
#pragma unroll
    for (int r = 0; r < 4; r++) {
        const int n = n0 + ty + 8 * r, k = k0 + tx;
        float v = tile[tx][ty + 8 * r];
        __nv_bfloat16 h = __float2bfloat16(v);
        __nv_bfloat16 l = __float2bfloat16(v - __bfloat162float(h));
        wt[(size_t)(hib + n) * CEMB + k] = h;
        wt[(size_t)(lob + n) * CEMB + k] = l;
    }
}

// ---------------- mma.sync split-bf16 GEMM -----------------------------------
// CTA 128(M) x 256(N), BK=64, 3-stage cp.async ring, 256 threads = 8 warps (2x4),
// warp tile 64x64 (LDSM:HMMA = 8:32 per k-chunk). Single barrier per iteration.
#define ASTG_BYTES  16384               // A stage: 128 x 64 bf16
#define BSTG_BYTES  32768               // B stage: 256 x 64 bf16
#define STAGE_BYTES (ASTG_BYTES + BSTG_BYTES)   // 49152
#define GSMEM_TOT   (3 * STAGE_BYTES)           // 147456

__global__ __launch_bounds__(256, 1) void mma_gemm(
    const __nv_bfloat16* __restrict__ A2, const __nv_bfloat16* __restrict__ Bt,
    float* __restrict__ C, int N, const float* __restrict__ scale_ptr, int m_base)
{
    extern __shared__ char smem[];
    const uint32_t sb = smem_u32(smem);
    const int tid  = threadIdx.x;
    const int wid  = tid >> 5, lane = tid & 31;
    const int wm   = wid >> 2, wn = wid & 3;     // 2 x 4 warps
    const int m0   = m_base + blockIdx.y * 128;
    const int n0   = blockIdx.x * 256;

    const int c  = tid & 7;        // 16B chunk within 128B row
    const int r0 = tid >> 3;       // 0..31

    const int NIT = 96;            // 3 terms x 32 BK64 steps

    auto load_stage = [&](int i) {
        const int s    = i % 3;
        const int term = i >> 5;
        const int k0   = (i & 31) * 64;
        const int aoff = (term == 2) ? 2048 : 0;
        const int brow = (term == 1) ? N : 0;
        const uint32_t da = sb + s * STAGE_BYTES;
        const uint32_t db = da + ASTG_BYTES;
        const __nv_bfloat16* Ap = A2 + (size_t)(m0 + r0) * 4096 + aoff + k0 + c * 8;
        const __nv_bfloat16* Bp = Bt + (size_t)(brow + n0 + r0) * 2048 + k0 + c * 8;
#pragma unroll
        for (int j = 0; j < 4; j++) {
            const int row = r0 + 32 * j;
            CP_ASYNC16(da + row * 128 + (((c ^ (row & 7))) << 4), Ap + (size_t)(32 * j) * 4096);
        }
#pragma unroll
        for (int j = 0; j < 8; j++) {
            const int row = r0 + 32 * j;
            CP_ASYNC16(db + row * 128 + (((c ^ (row & 7))) << 4), Bp + (size_t)(32 * j) * 2048);
        }
        CP_COMMIT();
    };

    const int lrow = lane & 15;
    const int lhi  = lane >> 4;

    int arow[4], brows[4];
#pragma unroll
    for (int mt = 0; mt < 4; mt++) arow[mt]  = wm * 64 + mt * 16 + lrow;
#pragma unroll
    for (int nt = 0; nt < 4; nt++) brows[nt] = wn * 64 + nt * 16 + lrow;

    float acc[4][8][4];
#pragma unroll
    for (int mt = 0; mt < 4; mt++)
#pragma unroll
        for (int j = 0; j < 8; j++)
#pragma unroll
            for (int e = 0; e < 4; e++) acc[mt][j][e] = 0.f;

    load_stage(0);
    load_stage(1);

    for (int i = 0; i < NIT; i++) {
        CP_WAIT1();
        __syncthreads();           // single barrier per iteration
        if (i + 2 < NIT) load_stage(i + 2);

        const uint32_t sa = sb + (i % 3) * STAGE_BYTES;
        const uint32_t sB = sa + ASTG_BYTES;

#pragma unroll
        for (int kk = 0; kk < 4; kk++) {
            const int chunk = kk * 2 + lhi;
            uint32_t a[4][4];
#pragma unroll
            for (int mt = 0; mt < 4; mt++) {
                const int row = arow[mt];
                ldm_x4(a[mt][0], a[mt][1], a[mt][2], a[mt][3],
                       sa + row * 128 + ((chunk ^ (row & 7)) << 4));
            }
            uint32_t bt[4][4];
#pragma unroll
            for (int nt = 0; nt < 4; nt++) {
                const int row = brows[nt];
                ldm_x4(bt[nt][0], bt[nt][1], bt[nt][2], bt[nt][3],
                       sB + row * 128 + ((chunk ^ (row & 7)) << 4));
            }
#pragma unroll
            for (int mt = 0; mt < 4; mt++)
#pragma unroll
                for (int j = 0; j < 8; j++) {
                    const int nt = j >> 1, h = j & 1;
                    mma_bf16(acc[mt][j][0], acc[mt][j][1], acc[mt][j][2], acc[mt][j][3],
                             a[mt][0], a[mt][1], a[mt][2], a[mt][3],
                             bt[nt][h], bt[nt][h + 2]);
                }
        }
    }

    const float sc = scale_ptr ? (1.0f + scale_ptr[0]) : 1.0f;
#pragma unroll
    for (int mt = 0; mt < 4; mt++) {
        const int r = m0 + wm * 64 + mt * 16 + (lane >> 2);
#pragma unroll
        for (int j = 0; j < 8; j++) {
            const int nt = j >> 1, h = j & 1;
            const int cb = n0 + wn * 64 + nt * 16 + h * 8 + 2 * (lane & 3);
            float2 v0 = make_float2(acc[mt][j][0] * sc, acc[mt][j][1] * sc);
            float2 v1 = make_float2(acc[mt][j][2] * sc, acc[mt][j][3] * sc);
            *(float2*)(C + (size_t)r * N + cb)       = v0;
            *(float2*)(C + (size_t)(r + 8) * N + cb) = v1;
        }
    }
}

// ---------------- fused prep: gates (v update + attn gate) + rope/rmsnorm ----
__global__ __launch_bounds__(128) void prep_kernel(
    const float* __restrict__ x, const float* __restrict__ ve,
    const float* __restrict__ wvg, const float* __restrict__ wag,
    const float* __restrict__ cosb, const float* __restrict__ sinb)
{
    const int tid = threadIdx.x;
    if (blockIdx.x < MROWS) {
        const int bt = blockIdx.x;
        __shared__ float xs[32];
        __shared__ float sg[8];

        if (tid < 32) xs[tid] = x[(size_t)bt * CEMB + tid];
        __syncthreads();

        if (tid < 8) {
            float s = 0.f;
#pragma unroll
            for (int c = 0; c < 32; c++) s += xs[c] * wvg[c * 8 + tid];
            sg[tid] = 2.0f / (1.0f + __expf(-s));
        } else if (tid >= 32 && tid < 48) {
            int h = tid - 32;
            float s = 0.f;
#pragma unroll
            for (int c = 0; c < 12; c++) s += xs[c] * wag[c * 16 + h];
            g_ag[(size_t)bt * NH + h] = 1.0f / (1.0f + __expf(-s));
        }
        __syncthreads();

        for (int i = tid; i < KVC; i += 128)
            g_qkv[(size_t)bt * 4096 + 3072 + i] += sg[i >> 7] * ve[(size_t)bt * KVC + i];
    } else {
        const int gw   = (blockIdx.x - MROWS) * 4 + (tid >> 5);
        const int lane = tid & 31;
        const int bt = gw / 24;
        const int hh = gw % 24;
        const int t  = bt % TSEQ;

        const float c0 = cosb[t * 64 + lane];
        const float c1 = cosb[t * 64 + lane + 32];
        const float s0 = sinb[t * 64 + lane];
        const float s1 = sinb[t * 64 + lane + 32];

        float t1a, t1b, t2a, t2b;
        float* dst;
        if (hh < 16) {
            const float* base = g_qkv + (size_t)bt * 4096 + hh * HD;
            t1a = base[lane];      t1b = base[lane + 32];
            t2a = base[64 + lane]; t2b = base[96 + lane];
            dst = g_qn + (size_t)bt * CEMB + hh * HD;
        } else {
            const int j = hh - 16;
            const float* base = g_qkv + (size_t)bt * 4096 + 2048 + j * HD;
            const int bt2 = (t == 0) ? bt : (bt - 1);
            const float* base2 = g_qkv + (size_t)bt2 * 4096 + 2048 + j * HD;
            t1a = base [lane];      t1b = base [lane + 32];
            t2a = base2[64 + lane]; t2b = base2[96 + lane];
            dst = g_kn + (size_t)bt * KVC + j * HD;
        }

        float o1a =  t1a * c0 + t2a * s0;
        float o1b =  t1b * c1 + t2b * s1;
        float o2a = -t1a * s0 + t2a * c0;
        float o2b = -t1b * s1 + t2b * c1;

        float ss = o1a * o1a + o1b * o1b + o2a * o2a + o2b * o2b;
#pragma unroll
        for (int o = 16; o > 0; o >>= 1) ss += __shfl_xor_sync(0xffffffffu, ss, o);
        const float r = rsqrtf(ss * (1.0f / 128.0f) + 1.1920929e-7f);

        dst[lane]      = o1a * r;
        dst[lane + 32] = o1b * r;
        dst[64 + lane] = o2a * r;
        dst[96 + lane] = o2b * r;
    }
}

// ---------------- branchless attention: 4 q-rows/thread, 16 dims/thread -------
#define KROW 160

__global__ __launch_bounds__(256, 1) void attn_kernel(const int* __restrict__ wsp)
{
    __shared__ __align__(16) float Ksm[32 * KROW];
    __shared__ __align__(16) float Vsm[32 * KROW];

    const int tile = blockIdx.x;
    const int bh   = blockIdx.y;
    const int b = bh / NH, h = bh % NH;
    const int kvh = h >> 1;
    const int tid = threadIdx.x;
    const int rowg = tid >> 3;
    const int oct  = tid & 7;
    const int q0   = tile * 128;

    int WS = wsp[0];
    if (WS <= 0 || WS > (1 << 20)) WS = 1024;
    const float QS = 0.088388347648318447f * 1.4426950408889634f;
    const float M2 = 16.33f;

    int qi[4];
#pragma unroll
    for (int r = 0; r < 4; r++) qi[r] = q0 + rowg * 4 + r;

    const int wq_lo = q0 + ((tid >> 5) << 4);
    const int wq_hi = wq_lo + 15;

    uint64_t q2[4][8];
#pragma unroll
    for (int r = 0; r < 4; r++) {
        const float* qp = g_qn + (size_t)(b * TSEQ + qi[r]) * CEMB + h * HD + oct * 16;
#pragma unroll
        for (int i = 0; i < 4; i++) {
            float4 v = *(const float4*)(qp + 4 * i);
            q2[r][2 * i]     = pk2(v.x * QS, v.y * QS);
            q2[r][2 * i + 1] = pk2(v.z * QS, v.w * QS);
        }
    }

    uint64_t acc[4][8];
#pragma unroll
    for (int r = 0; r < 4; r++)
#pragma unroll
        for (int i = 0; i < 8; i++) acc[r][i] = 0ull;
    float lsum[4] = {0.f, 0.f, 0.f, 0.f};

    int kmin = q0 - WS; if (kmin < 0) kmin = 0;
    const int kt0 = kmin & ~31;

    for (int kt = kt0; kt <= q0 + 127; kt += 32) {
        __syncthreads();
        {
            const float* Kb = g_kn  + (size_t)(b * TSEQ + kt) * KVC + kvh * HD;
            const float* Vb = g_qkv + (size_t)(b * TSEQ + kt) * 4096 + 3072 + kvh * HD;
#pragma unroll
            for (int i = 0; i < 4; i++) {
                const int f   = i * 256 + tid;
                const int r   = f >> 5;
                const int c4  = f & 31;
                const int dst = r * KROW + (c4 >> 2) * 20 + (c4 & 3) * 4;
                *(float4*)(Ksm + dst) = *(const float4*)(Kb + (size_t)r * KVC  + c4 * 4);
                *(float4*)(Vsm + dst) = *(const float4*)(Vb + (size_t)r * 4096 + c4 * 4);
            }
        }
        __syncthreads();

        if (kt > wq_hi || kt + 31 < wq_lo - WS) continue;

#pragma unroll 1
        for (int j0 = 0; j0 < 32; j0 += 4) {
            float sv[4][4];
#pragma unroll
            for (int jj = 0; jj < 4; jj++) {
                const float4* kr4 = (const float4*)(Ksm + (j0 + jj) * KROW + oct * 20);
                float4 k0 = kr4[0], k1 = kr4[1], k2 = kr4[2], k3 = kr4[3];
                const uint64_t kp0 = pk2(k0.x, k0.y), kp1 = pk2(k0.z, k0.w);
                const uint64_t kp2 = pk2(k1.x, k1.y), kp3 = pk2(k1.z, k1.w);
                const uint64_t kp4 = pk2(k2.x, k2.y), kp5 = pk2(k2.z, k2.w);
                const uint64_t kp6 = pk2(k3.x, k3.y), kp7 = pk2(k3.z, k3.w);
#pragma unroll
                for (int r = 0; r < 4; r++) {
                    uint64_t d0 = 0ull, d1 = 0ull;
                    d0 = fma2(q2[r][0], kp0, d0);
                    d1 = fma2(q2[r][1], kp1, d1);
                    d0 = fma2(q2[r][2], kp2, d0);
                    d1 = fma2(q2[r][3], kp3, d1);
                    d0 = fma2(q2[r][4], kp4, d0);
                    d1 = fma2(q2[r][5], kp5, d1);
                    d0 = fma2(q2[r][6], kp6, d0);
                    d1 = fma2(q2[r][7], kp7, d1);
                    float2 e0 = upk2(d0), e1 = upk2(d1);
                    sv[jj][r] = (e0.x + e0.y) + (e1.x + e1.y);
                }
            }
#pragma unroll
            for (int jj = 0; jj < 4; jj++)
#pragma unroll
                for (int r = 0; r < 4; r++)
                    sv[jj][r] += __shfl_xor_sync(0xffffffffu, sv[jj][r], 1);
#pragma unroll
            for (int jj = 0; jj < 4; jj++)
#pragma unroll
                for (int r = 0; r < 4; r++)
                    sv[jj][r] += __shfl_xor_sync(0xffffffffu, sv[jj][r], 2);
#pragma unroll
            for (int jj = 0; jj < 4; jj++)
#pragma unroll
                for (int r = 0; r < 4; r++)
                    sv[jj][r] += __shfl_xor_sync(0xffffffffu, sv[jj][r], 4);

            float pv[4][4];
#pragma unroll
            for (int jj = 0; jj < 4; jj++)
#pragma unroll
                for (int r = 0; r < 4; r++) {
                    const int kj = kt + j0 + jj;
                    const bool valid = (kj <= qi[r]) && (kj >= qi[r] - WS);
                    const float e = ex2f(sv[jj][r] - M2);
                    pv[jj][r] = valid ? e : 0.f;
                    lsum[r] += pv[jj][r];
                }

#pragma unroll
            for (int jj = 0; jj < 4; jj++) {
                const float4* vr4 = (const float4*)(Vsm + (j0 + jj) * KROW + oct * 20);
                float4 v0 = vr4[0], v1 = vr4[1], v2 = vr4[2], v3 = vr4[3];
                const uint64_t vp0 = pk2(v0.x, v0.y), vp1 = pk2(v0.z, v0.w);
                const uint64_t vp2 = pk2(v1.x, v1.y), vp3 = pk2(v1.z, v1.w);
                const uint64_t vp4 = pk2(v2.x, v2.y), vp5 = pk2(v2.z, v2.w);
                const uint64_t vp6 = pk2(v3.x, v3.y), vp7 = pk2(v3.z, v3.w);
#pragma unroll
                for (int r = 0; r < 4; r++) {
                    const uint64_t pp = pk2(pv[jj][r], pv[jj][r]);
                    acc[r][0] = fma2(pp, vp0, acc[r][0]);
                    acc[r][1] = fma2(pp, vp1, acc[r][1]);
                    acc[r][2] = fma2(pp, vp2, acc[r][2]);
                    acc[r][3] = fma2(pp, vp3, acc[r][3]);
                    acc[r][4] = fma2(pp, vp4, acc[r][4]);
                    acc[r][5] = fma2(pp, vp5, acc[r][5]);
                    acc[r][6] = fma2(pp, vp6, acc[r][6]);
                    acc[r][7] = fma2(pp, vp7, acc[r][7]);
                }
            }
        }
    }

#pragma unroll
    for (int r = 0; r < 4; r++) {
        const float ag  = g_ag[(size_t)(b * TSEQ + qi[r]) * NH + h];
        const float inv = ag / lsum[r];
        __nv_bfloat16* base = g_y2 + (size_t)(b * TSEQ + qi[r]) * 4096 + h * HD + oct * 16;
#pragma unroll
        for (int i = 0; i < 8; i++) {
            float2 a = upk2(acc[r][i]);
            const float f0 = a.x * inv, f1 = a.y * inv;
            __nv_bfloat16 h0 = __float2bfloat16(f0);
            __nv_bfloat16 h1 = __float2bfloat16(f1);
            __nv_bfloat16 l0 = __float2bfloat16(f0 - __bfloat162float(h0));
            __nv_bfloat16 l1 = __float2bfloat16(f1 - __bfloat162float(h1));
            *(__nv_bfloat162*)(base + 2 * i)        = __nv_bfloat162(h0, h1);
            *(__nv_bfloat162*)(base + 2048 + 2 * i) = __nv_bfloat162(l0, l1);
        }
    }
}

// ---------------- launcher ---------------------------------------------------
extern "C" void kernel_launch(void* const* d_in, const int* in_sizes, int n_in,
                              void* d_out, int out_size)
{
    const float* x     = (const float*)d_in[0];
    const float* ve    = (const float*)d_in[1];
    const float* cosb  = (const float*)d_in[2];
    const float* sinb  = (const float*)d_in[3];
    const float* wq    = (const float*)d_in[4];
    const float* wk    = (const float*)d_in[5];
    const float* wv    = (const float*)d_in[6];
    const float* wproj = (const float*)d_in[7];
    const float* wvg   = (const float*)d_in[8];
    const float* wag   = (const float*)d_in[9];
    const float* ps    = (const float*)d_in[10];
    const int*   wsp   = (const int*)  d_in[11];
    float* out = (float*)d_out;

    float *pqkv;
    __nv_bfloat16 *px2, *py2, *pwqkvt, *pwpt;
    cudaGetSymbolAddress((void**)&pqkv,   g_qkv);
    cudaGetSymbolAddress((void**)&px2,    g_x2);
    cudaGetSymbolAddress((void**)&py2,    g_y2);
    cudaGetSymbolAddress((void**)&pwqkvt, g_wqkvt);
    cudaGetSymbolAddress((void**)&pwpt,   g_wpt);

    cudaFuncSetAttribute(mma_gemm, cudaFuncAttributeMaxDynamicSharedMemorySize, GSMEM_TOT);

    // 1: all operand conversions in one launch
    conv_all<<<20480, 256>>>(x, wq, wk, wv, wproj, px2, pwqkvt, pwpt);
    // 2: fused QKV projection (N=4096), CTA tile 128x256
    mma_gemm<<<dim3(16, MROWS / 128), 256, GSMEM_TOT>>>(px2, pwqkvt, pqkv, 4096, nullptr, 0);
    // 3: fused gates + rope/rmsnorm
    prep_kernel<<<MROWS + MROWS * 24 / 4, 128>>>(x, ve, wvg, wag, cosb, sinb);
    // 4: attention — writes split-bf16 y directly
    attn_kernel<<<dim3(TSEQ / 128, BATCH * NH), 256>>>(wsp);
    // 5: output projection
    mma_gemm<<<dim3(8, MROWS / 128), 256, GSMEM_TOT>>>(py2, pwpt, out, CEMB, ps, 0);
}

// round 13
// speedup vs baseline: 1.0497x; 1.0497x over previous
#include <cuda_runtime.h>
#include <cuda_bf16.h>
#include <math.h>
#include <stdint.h>

#define NH    16
#define NKV   8
#define HD    128
#define CEMB  2048
#define BATCH 2
#define TSEQ  2048
#define MROWS (BATCH * TSEQ)
#define KVC   (NKV * HD)   // 1024

// ---------------- scratch ----------------------------------------------------
__device__ float g_qkv[MROWS * 4096];   // per row: q(2048) | k(1024) | v(1024)
__device__ float g_qn [MROWS * CEMB];
__device__ float g_kn [MROWS * KVC];
__device__ float g_ag [MROWS * NH];

__device__ __nv_bfloat16 g_x2   [MROWS * 2 * CEMB];
__device__ __nv_bfloat16 g_y2   [MROWS * 2 * CEMB];   // attention writes this directly
__device__ __nv_bfloat16 g_wqkvt[2 * 4096 * CEMB];
__device__ __nv_bfloat16 g_wpt  [2 * CEMB * CEMB];

// ---------------- helpers ----------------------------------------------------
__device__ __forceinline__ uint32_t smem_u32(const void* p) {
    uint32_t a;
    asm("{ .reg .u64 t; cvta.to.shared.u64 t, %1; cvt.u32.u64 %0, t; }" : "=r"(a) : "l"(p));
    return a;
}
#define CP_ASYNC16(dst, src) \
    asm volatile("cp.async.cg.shared.global [%0], [%1], 16;" :: "r"(dst), "l"(src))
#define CP_COMMIT() asm volatile("cp.async.commit_group;" ::: "memory")
#define CP_WAIT1()  asm volatile("cp.async.wait_group 1;" ::: "memory")
#define CP_WAIT0()  asm volatile("cp.async.wait_group 0;" ::: "memory")

__device__ __forceinline__ void ldm_x4(uint32_t& r0, uint32_t& r1, uint32_t& r2, uint32_t& r3,
                                       uint32_t addr) {
    asm volatile("ldmatrix.sync.aligned.m8n8.x4.shared.b16 {%0,%1,%2,%3}, [%4];"
                 : "=r"(r0), "=r"(r1), "=r"(r2), "=r"(r3) : "r"(addr));
}
__device__ __forceinline__ void mma_bf16(float& d0, float& d1, float& d2, float& d3,
                                         uint32_t a0, uint32_t a1, uint32_t a2, uint32_t a3,
                                         uint32_t b0, uint32_t b1) {
    asm volatile("mma.sync.aligned.m16n8k16.row.col.f32.bf16.bf16.f32 "
                 "{%0,%1,%2,%3}, {%4,%5,%6,%7}, {%8,%9}, {%0,%1,%2,%3};"
                 : "+f"(d0), "+f"(d1), "+f"(d2), "+f"(d3)
                 : "r"(a0), "r"(a1), "r"(a2), "r"(a3), "r"(b0), "r"(b1));
}

// ---------------- packed fp32x2 + fast exp2 ----------------------------------
__device__ __forceinline__ uint64_t pk2(float lo, float hi) {
    float2 f = make_float2(lo, hi);
    return *reinterpret_cast<uint64_t*>(&f);
}
__device__ __forceinline__ float2 upk2(uint64_t u) {
    return *reinterpret_cast<float2*>(&u);
}
__device__ __forceinline__ uint64_t fma2(uint64_t a, uint64_t b, uint64_t c) {
    uint64_t d;
    asm("fma.rn.f32x2 %0, %1, %2, %3;" : "=l"(d) : "l"(a), "l"(b), "l"(c));
    return d;
}
__device__ __forceinline__ float ex2f(float x) {
    float y;
    asm("ex2.approx.f32 %0, %1;" : "=f"(y) : "f"(x));
    return y;
}

// ---------------- fused operand conversion (one launch) ----------------------
__global__ __launch_bounds__(256) void conv_all(
    const float* __restrict__ x,
    const float* __restrict__ wq, const float* __restrict__ wk,
    const float* __restrict__ wv, const float* __restrict__ wproj,
    __nv_bfloat16* __restrict__ x2,
    __nv_bfloat16* __restrict__ wqkvt, __nv_bfloat16* __restrict__ wpt)
{
    const int tid = threadIdx.x;
    if (blockIdx.x < 8192) {
        const int idx = (blockIdx.x * 256 + tid) * 4;
        const int row = idx >> 11;
        const int col = idx & 2047;
        float4 v = *(const float4*)(x + (size_t)row * CEMB + col);
        __nv_bfloat16 h0 = __float2bfloat16(v.x), h1 = __float2bfloat16(v.y);
        __nv_bfloat16 h2 = __float2bfloat16(v.z), h3 = __float2bfloat16(v.w);
        __nv_bfloat16 l0 = __float2bfloat16(v.x - __bfloat162float(h0));
        __nv_bfloat16 l1 = __float2bfloat16(v.y - __bfloat162float(h1));
        __nv_bfloat16 l2 = __float2bfloat16(v.z - __bfloat162float(h2));
        __nv_bfloat16 l3 = __float2bfloat16(v.w - __bfloat162float(h3));
        __nv_bfloat16* base = x2 + (size_t)row * 4096;
        *(__nv_bfloat162*)(base + col)            = __nv_bfloat162(h0, h1);
        *(__nv_bfloat162*)(base + col + 2)        = __nv_bfloat162(h2, h3);
        *(__nv_bfloat162*)(base + 2048 + col)     = __nv_bfloat162(l0, l1);
        *(__nv_bfloat162*)(base + 2048 + col + 2) = __nv_bfloat162(l2, l3);
        return;
    }
    __shared__ float tile[32][33];
    const int fidx = blockIdx.x - 8192;
    const int bx = fidx % 192;
    const int ky = fidx / 192;
    const float* w; __nv_bfloat16* wt;
    int N_src, hib, lob, n0;
    if (bx < 64)       { w = wq;    wt = wqkvt; N_src = 2048; hib = 0;    lob = 4096; n0 = bx * 32; }
    else if (bx < 96)  { w = wk;    wt = wqkvt; N_src = 1024; hib = 2048; lob = 6144; n0 = (bx - 64) * 32; }
    else if (bx < 128) { w = wv;    wt = wqkvt; N_src = 1024; hib = 3072; lob = 7168; n0 = (bx - 96) * 32; }
    else               { w = wproj; wt = wpt;   N_src = 2048; hib = 0;    lob = 2048; n0 = (bx - 128) * 32; }

    const int k0 = ky * 32;
    const int tx = tid & 31, ty = tid >> 5;
#pragma unroll
    for (int r = 0; r < 4; r++)
        tile[ty + 8 * r][tx] = w[(size_t)(k0 + ty + 8 * r) * N_src + n0 + tx];
    __syncthreads();
#pragma unroll
    for (int r = 0; r < 4; r++) {
        const int n = n0 + ty + 8 * r, k = k0 + tx;
        float v = tile[tx][ty + 8 * r];
        __nv_bfloat16 h = __float2bfloat16(v);
        __nv_bfloat16 l = __float2bfloat16(v - __bfloat162float(h));
        wt[(size_t)(hib + n) * CEMB + k] = h;
        wt[(size_t)(lob + n) * CEMB + k] = l;
    }
}

// ---------------- mma.sync split-bf16 GEMM (R11-proven shape) -----------------
// CTA 128x128, BK=64, 3-stage cp.async ring, 8 warps (4x2), warp tile 32x64.
#define STAGE_BYTES 32768               // A 16KB + B 16KB
#define GSMEM_TOT   (3 * STAGE_BYTES)   // 98304

__global__ __launch_bounds__(256) void mma_gemm(
    const __nv_bfloat16* __restrict__ A2, const __nv_bfloat16* __restrict__ Bt,
    float* __restrict__ C, int N, const float* __restrict__ scale_ptr, int m_base)
{
    extern __shared__ char smem[];
    const uint32_t sb = smem_u32(smem);
    const int tid  = threadIdx.x;
    const int wid  = tid >> 5, lane = tid & 31;
    const int wm   = wid >> 1, wn = wid & 1;
    const int m0   = m_base + blockIdx.y * 128;
    const int n0   = blockIdx.x * 128;

    const int c  = tid & 7;
    const int r0 = tid >> 3;

    const int NIT = 96;

    auto load_stage = [&](int i) {
        const int s    = i % 3;
        const int term = i >> 5;
        const int k0   = (i & 31) * 64;
        const int aoff = (term == 2) ? 2048 : 0;
        const int brow = (term == 1) ? N : 0;
        const uint32_t da = sb + s * STAGE_BYTES;
        const uint32_t db = da + 16384;
        const __nv_bfloat16* Ap = A2 + (size_t)(m0 + r0) * 4096 + aoff + k0 + c * 8;
        const __nv_bfloat16* Bp = Bt + (size_t)(brow + n0 + r0) * 2048 + k0 + c * 8;
#pragma unroll
        for (int j = 0; j < 4; j++) {
            const int row = r0 + 32 * j;
            CP_ASYNC16(da + row * 128 + (((c ^ (row & 7))) << 4), Ap + (size_t)(32 * j) * 4096);
            CP_ASYNC16(db + row * 128 + (((c ^ (row & 7))) << 4), Bp + (size_t)(32 * j) * 2048);
        }
        CP_COMMIT();
    };

    const int lrow = lane & 15;
    const int lhi  = lane >> 4;

    int arow[2], brows[4];
#pragma unroll
    for (int mt = 0; mt < 2; mt++) arow[mt]  = wm * 32 + mt * 16 + lrow;
#pragma unroll
    for (int nt = 0; nt < 4; nt++) brows[nt] = wn * 64 + nt * 16 + lrow;

    float acc[2][8][4];
#pragma unroll
    for (int mt = 0; mt < 2; mt++)
#pragma unroll
        for (int j = 0; j < 8; j++)
#pragma unroll
            for (int e = 0; e < 4; e++) acc[mt][j][e] = 0.f;

    load_stage(0);
    load_stage(1);

    for (int i = 0; i < NIT; i++) {
        CP_WAIT1();
        __syncthreads();
        if (i + 2 < NIT) load_stage(i + 2);

        const uint32_t sa = sb + (i % 3) * STAGE_BYTES;
        const uint32_t sB = sa + 16384;

#pragma unroll
        for (int kk = 0; kk < 4; kk++) {
            const int chunk = kk * 2 + lhi;
            uint32_t a[2][4];
#pragma unroll
            for (int mt = 0; mt < 2; mt++) {
                const int row = arow[mt];
                ldm_x4(a[mt][0], a[mt][1], a[mt][2], a[mt][3],
                       sa + row * 128 + ((chunk ^ (row & 7)) << 4));
            }
            uint32_t bt[4][4];
#pragma unroll
            for (int nt = 0; nt < 4; nt++) {
                const int row = brows[nt];
                ldm_x4(bt[nt][0], bt[nt][1], bt[nt][2], bt[nt][3],
                       sB + row * 128 + ((chunk ^ (row & 7)) << 4));
            }
#pragma unroll
            for (int mt = 0; mt < 2; mt++)
#pragma unroll
                for (int j = 0; j < 8; j++) {
                    const int nt = j >> 1, h = j & 1;
                    mma_bf16(acc[mt][j][0], acc[mt][j][1], acc[mt][j][2], acc[mt][j][3],
                             a[mt][0], a[mt][1], a[mt][2], a[mt][3],
                             bt[nt][h], bt[nt][h + 2]);
                }
        }
    }

    const float sc = scale_ptr ? (1.0f + scale_ptr[0]) : 1.0f;
#pragma unroll
    for (int mt = 0; mt < 2; mt++) {
        const int r = m0 + wm * 32 + mt * 16 + (lane >> 2);
#pragma unroll
        for (int j = 0; j < 8; j++) {
            const int cb = n0 + wn * 64 + j * 8 + 2 * (lane & 3);
            float2 v0 = make_float2(acc[mt][j][0] * sc, acc[mt][j][1] * sc);
            float2 v1 = make_float2(acc[mt][j][2] * sc, acc[mt][j][3] * sc);
            *(float2*)(C + (size_t)r * N + cb)       = v0;
            *(float2*)(C + (size_t)(r + 8) * N + cb) = v1;
        }
    }
}

// ---------------- fused prep: gates (v update + attn gate) + rope/rmsnorm ----
__global__ __launch_bounds__(128) void prep_kernel(
    const float* __restrict__ x, const float* __restrict__ ve,
    const float* __restrict__ wvg, const float* __restrict__ wag,
    const float* __restrict__ cosb, const float* __restrict__ sinb)
{
    const int tid = threadIdx.x;
    if (blockIdx.x < MROWS) {
        const int bt = blockIdx.x;
        __shared__ float xs[32];
        __shared__ float sg[8];

        if (tid < 32) xs[tid] = x[(size_t)bt * CEMB + tid];
        __syncthreads();

        if (tid < 8) {
            float s = 0.f;
#pragma unroll
            for (int c = 0; c < 32; c++) s += xs[c] * wvg[c * 8 + tid];
            sg[tid] = 2.0f / (1.0f + __expf(-s));
        } else if (tid >= 32 && tid < 48) {
            int h = tid - 32;
            float s = 0.f;
#pragma unroll
            for (int c = 0; c < 12; c++) s += xs[c] * wag[c * 16 + h];
            g_ag[(size_t)bt * NH + h] = 1.0f / (1.0f + __expf(-s));
        }
        __syncthreads();

        for (int i = tid; i < KVC; i += 128)
            g_qkv[(size_t)bt * 4096 + 3072 + i] += sg[i >> 7] * ve[(size_t)bt * KVC + i];
    } else {
        const int gw   = (blockIdx.x - MROWS) * 4 + (tid >> 5);
        const int lane = tid & 31;
        const int bt = gw / 24;
        const int hh = gw % 24;
        const int t  = bt % TSEQ;

        const float c0 = cosb[t * 64 + lane];
        const float c1 = cosb[t * 64 + lane + 32];
        const float s0 = sinb[t * 64 + lane];
        const float s1 = sinb[t * 64 + lane + 32];

        float t1a, t1b, t2a, t2b;
        float* dst;
        if (hh < 16) {
            const float* base = g_qkv + (size_t)bt * 4096 + hh * HD;
            t1a = base[lane];      t1b = base[lane + 32];
            t2a = base[64 + lane]; t2b = base[96 + lane];
            dst = g_qn + (size_t)bt * CEMB + hh * HD;
        } else {
            const int j = hh - 16;
            const float* base = g_qkv + (size_t)bt * 4096 + 2048 + j * HD;
            const int bt2 = (t == 0) ? bt : (bt - 1);
            const float* base2 = g_qkv + (size_t)bt2 * 4096 + 2048 + j * HD;
            t1a = base [lane];      t1b = base [lane + 32];
            t2a = base2[64 + lane]; t2b = base2[96 + lane];
            dst = g_kn + (size_t)bt * KVC + j * HD;
        }

        float o1a =  t1a * c0 + t2a * s0;
        float o1b =  t1b * c1 + t2b * s1;
        float o2a = -t1a * s0 + t2a * c0;
        float o2b = -t1b * s1 + t2b * c1;

        float ss = o1a * o1a + o1b * o1b + o2a * o2a + o2b * o2b;
#pragma unroll
        for (int o = 16; o > 0; o >>= 1) ss += __shfl_xor_sync(0xffffffffu, ss, o);
        const float r = rsqrtf(ss * (1.0f / 128.0f) + 1.1920929e-7f);

        dst[lane]      = o1a * r;
        dst[lane + 32] = o1b * r;
        dst[64 + lane] = o2a * r;
        dst[96 + lane] = o2b * r;
    }
}

// ---------------- branchless attention: 4 q-rows/thread, cp.async double buf --
// 256 threads: thread = (rowg = tid>>3, oct = tid&7). K/V tiles stream via
// cp.async into two 40KB buffers while the previous tile computes.
#define KROW   160
#define TILE_F (32 * KROW)              // 5120 floats per K (or V) tile
#define ASMEM_TOT (4 * TILE_F * 4)      // K0,V0,K1,V1 = 81920 bytes

__global__ __launch_bounds__(256, 1) void attn_kernel(const int* __restrict__ wsp)
{
    extern __shared__ __align__(16) float dsm[];
    // layout: [K0 | V0 | K1 | V1], each TILE_F floats

    const int tile = blockIdx.x;
    const int bh   = blockIdx.y;
    const int b = bh / NH, h = bh % NH;
    const int kvh = h >> 1;
    const int tid = threadIdx.x;
    const int rowg = tid >> 3;
    const int oct  = tid & 7;
    const int q0   = tile * 128;

    int WS = wsp[0];
    if (WS <= 0 || WS > (1 << 20)) WS = 1024;
    const float QS = 0.088388347648318447f * 1.4426950408889634f;
    const float M2 = 16.33f;

    int qi[4];
#pragma unroll
    for (int r = 0; r < 4; r++) qi[r] = q0 + rowg * 4 + r;

    const int wq_lo = q0 + ((tid >> 5) << 4);
    const int wq_hi = wq_lo + 15;

    uint64_t q2[4][8];
#pragma unroll
    for (int r = 0; r < 4; r++) {
        const float* qp = g_qn + (size_t)(b * TSEQ + qi[r]) * CEMB + h * HD + oct * 16;
#pragma unroll
        for (int i = 0; i < 4; i++) {
            float4 v = *(const float4*)(qp + 4 * i);
            q2[r][2 * i]     = pk2(v.x * QS, v.y * QS);
            q2[r][2 * i + 1] = pk2(v.z * QS, v.w * QS);
        }
    }

    uint64_t acc[4][8];
#pragma unroll
    for (int r = 0; r < 4; r++)
#pragma unroll
        for (int i = 0; i < 8; i++) acc[r][i] = 0ull;
    float lsum[4] = {0.f, 0.f, 0.f, 0.f};

    int kmin = q0 - WS; if (kmin < 0) kmin = 0;
    const int kt0 = kmin & ~31;
    const int ktEnd = q0 + 127;     // last tile start <= ktEnd

    // per-thread fixed copy coordinates (4 chunks)
    int cp_r[4], cp_dstb[4];
#pragma unroll
    for (int i = 0; i < 4; i++) {
        const int f  = i * 256 + tid;
        const int r  = f >> 5;
        const int c4 = f & 31;
        cp_r[i]    = r;
        cp_dstb[i] = (r * KROW + (c4 >> 2) * 20 + (c4 & 3) * 4) * 4;   // bytes
    }
    const uint32_t kbase[2] = { smem_u32(dsm),              smem_u32(dsm + 2 * TILE_F) };
    const uint32_t vbase[2] = { smem_u32(dsm + TILE_F),     smem_u32(dsm + 3 * TILE_F) };

    auto load_tile = [&](int kt, int s) {
        const float* Kg = g_kn  + (size_t)(b * TSEQ + kt) * KVC + kvh * HD;
        const float* Vg = g_qkv + (size_t)(b * TSEQ + kt) * 4096 + 3072 + kvh * HD;
#pragma unroll
        for (int i = 0; i < 4; i++) {
            const int c4 = (i * 256 + tid) & 31;
            CP_ASYNC16(kbase[s] + cp_dstb[i], Kg + (size_t)cp_r[i] * KVC  + c4 * 4);
            CP_ASYNC16(vbase[s] + cp_dstb[i], Vg + (size_t)cp_r[i] * 4096 + c4 * 4);
        }
        CP_COMMIT();
    };

    load_tile(kt0, 0);
    int s = 0;
    for (int kt = kt0; kt <= ktEnd; kt += 32, s ^= 1) {
        if (kt + 32 <= ktEnd) { load_tile(kt + 32, s ^ 1); CP_WAIT1(); }
        else                  { CP_WAIT0(); }
        __syncthreads();                       // tile kt visible in buffer s

        if (!(kt > wq_hi || kt + 31 < wq_lo - WS)) {
            const float* ksm = dsm + (s ? 2 * TILE_F : 0);
            const float* vsm = dsm + (s ? 3 * TILE_F : TILE_F);

#pragma unroll 1
            for (int j0 = 0; j0 < 32; j0 += 4) {
                float sv[4][4];
#pragma unroll
                for (int jj = 0; jj < 4; jj++) {
                    const float4* kr4 = (const float4*)(ksm + (j0 + jj) * KROW + oct * 20);
                    float4 k0 = kr4[0], k1 = kr4[1], k2 = kr4[2], k3 = kr4[3];
                    const uint64_t kp0 = pk2(k0.x, k0.y), kp1 = pk2(k0.z, k0.w);
                    const uint64_t kp2 = pk2(k1.x, k1.y), kp3 = pk2(k1.z, k1.w);
                    const uint64_t kp4 = pk2(k2.x, k2.y), kp5 = pk2(k2.z, k2.w);
                    const uint64_t kp6 = pk2(k3.x, k3.y), kp7 = pk2(k3.z, k3.w);
#pragma unroll
                    for (int r = 0; r < 4; r++) {
                        uint64_t d0 = 0ull, d1 = 0ull;
                        d0 = fma2(q2[r][0], kp0, d0);
                        d1 = fma2(q2[r][1], kp1, d1);
                        d0 = fma2(q2[r][2], kp2, d0);
                        d1 = fma2(q2[r][3], kp3, d1);
                        d0 = fma2(q2[r][4], kp4, d0);
                        d1 = fma2(q2[r][5], kp5, d1);
                        d0 = fma2(q2[r][6], kp6, d0);
                        d1 = fma2(q2[r][7], kp7, d1);
                        float2 e0 = upk2(d0), e1 = upk2(d1);
                        sv[jj][r] = (e0.x + e0.y) + (e1.x + e1.y);
                    }
                }
#pragma unroll
                for (int jj = 0; jj < 4; jj++)
#pragma unroll
                    for (int r = 0; r < 4; r++)
                        sv[jj][r] += __shfl_xor_sync(0xffffffffu, sv[jj][r], 1);
#pragma unroll
                for (int jj = 0; jj < 4; jj++)
#pragma unroll
                    for (int r = 0; r < 4; r++)
                        sv[jj][r] += __shfl_xor_sync(0xffffffffu, sv[jj][r], 2);
#pragma unroll
                for (int jj = 0; jj < 4; jj++)
#pragma unroll
                    for (int r = 0; r < 4; r++)
                        sv[jj][r] += __shfl_xor_sync(0xffffffffu, sv[jj][r], 4);

                float pv[4][4];
#pragma unroll
                for (int jj = 0; jj < 4; jj++)
#pragma unroll
                    for (int r = 0; r < 4; r++) {
                        const int kj = kt + j0 + jj;
                        const bool valid = (kj <= qi[r]) && (kj >= qi[r] - WS);
                        const float e = ex2f(sv[jj][r] - M2);
                        pv[jj][r] = valid ? e : 0.f;
                        lsum[r] += pv[jj][r];
                    }

#pragma unroll
                for (int jj = 0; jj < 4; jj++) {
                    const float4* vr4 = (const float4*)(vsm + (j0 + jj) * KROW + oct * 20);
                    float4 v0 = vr4[0], v1 = vr4[1], v2 = vr4[2], v3 = vr4[3];
                    const uint64_t vp0 = pk2(v0.x, v0.y), vp1 = pk2(v0.z, v0.w);
                    const uint64_t vp2 = pk2(v1.x, v1.y), vp3 = pk2(v1.z, v1.w);
                    const uint64_t vp4 = pk2(v2.x, v2.y), vp5 = pk2(v2.z, v2.w);
                    const uint64_t vp6 = pk2(v3.x, v3.y), vp7 = pk2(v3.z, v3.w);
#pragma unroll
                    for (int r = 0; r < 4; r++) {
                        const uint64_t pp = pk2(pv[jj][r], pv[jj][r]);
                        acc[r][0] = fma2(pp, vp0, acc[r][0]);
                        acc[r][1] = fma2(pp, vp1, acc[r][1]);
                        acc[r][2] = fma2(pp, vp2, acc[r][2]);
                        acc[r][3] = fma2(pp, vp3, acc[r][3]);
                        acc[r][4] = fma2(pp, vp4, acc[r][4]);
                        acc[r][5] = fma2(pp, vp5, acc[r][5]);
                        acc[r][6] = fma2(pp, vp6, acc[r][6]);
                        acc[r][7] = fma2(pp, vp7, acc[r][7]);
                    }
                }
            }
        }
        __syncthreads();                       // protect buffer s from next refill
    }

#pragma unroll
    for (int r = 0; r < 4; r++) {
        const float ag  = g_ag[(size_t)(b * TSEQ + qi[r]) * NH + h];
        const float inv = ag / lsum[r];
        __nv_bfloat16* base = g_y2 + (size_t)(b * TSEQ + qi[r]) * 4096 + h * HD + oct * 16;
#pragma unroll
        for (int i = 0; i < 8; i++) {
            float2 a = upk2(acc[r][i]);
            const float f0 = a.x * inv, f1 = a.y * inv;
            __nv_bfloat16 h0 = __float2bfloat16(f0);
            __nv_bfloat16 h1 = __float2bfloat16(f1);
            __nv_bfloat16 l0 = __float2bfloat16(f0 - __bfloat162float(h0));
            __nv_bfloat16 l1 = __float2bfloat16(f1 - __bfloat162float(h1));
            *(__nv_bfloat162*)(base + 2 * i)        = __nv_bfloat162(h0, h1);
            *(__nv_bfloat162*)(base + 2048 + 2 * i) = __nv_bfloat162(l0, l1);
        }
    }
}

// ---------------- launcher ---------------------------------------------------
extern "C" void kernel_launch(void* const* d_in, const int* in_sizes, int n_in,
                              void* d_out, int out_size)
{
    const float* x     = (const float*)d_in[0];
    const float* ve    = (const float*)d_in[1];
    const float* cosb  = (const float*)d_in[2];
    const float* sinb  = (const float*)d_in[3];
    const float* wq    = (const float*)d_in[4];
    const float* wk    = (const float*)d_in[5];
    const float* wv    = (const float*)d_in[6];
    const float* wproj = (const float*)d_in[7];
    const float* wvg   = (const float*)d_in[8];
    const float* wag   = (const float*)d_in[9];
    const float* ps    = (const float*)d_in[10];
    const int*   wsp   = (const int*)  d_in[11];
    float* out = (float*)d_out;

    float *pqkv;
    __nv_bfloat16 *px2, *py2, *pwqkvt, *pwpt;
    cudaGetSymbolAddress((void**)&pqkv,   g_qkv);
    cudaGetSymbolAddress((void**)&px2,    g_x2);
    cudaGetSymbolAddress((void**)&py2,    g_y2);
    cudaGetSymbolAddress((void**)&pwqkvt, g_wqkvt);
    cudaGetSymbolAddress((void**)&pwpt,   g_wpt);

    cudaFuncSetAttribute(mma_gemm, cudaFuncAttributeMaxDynamicSharedMemorySize, GSMEM_TOT);
    cudaFuncSetAttribute(attn_kernel, cudaFuncAttributeMaxDynamicSharedMemorySize, ASMEM_TOT);

    // 1: all operand conversions in one launch
    conv_all<<<20480, 256>>>(x, wq, wk, wv, wproj, px2, pwqkvt, pwpt);
    // 2: fused QKV projection (N=4096)
    mma_gemm<<<dim3(32, MROWS / 128), 256, GSMEM_TOT>>>(px2, pwqkvt, pqkv, 4096, nullptr, 0);
    // 3: fused gates + rope/rmsnorm
    prep_kernel<<<MROWS + MROWS * 24 / 4, 128>>>(x, ve, wvg, wag, cosb, sinb);
    // 4: attention — double-buffered K/V, writes split-bf16 y directly
    attn_kernel<<<dim3(TSEQ / 128, BATCH * NH), 256, ASMEM_TOT>>>(wsp);
    // 5: output projection
    mma_gemm<<<dim3(16, MROWS / 128), 256, GSMEM_TOT>>>(py2, pwpt, out, CEMB, ps, 0);
}

// round 14
// speedup vs baseline: 1.0530x; 1.0031x over previous
#include <cuda_runtime.h>
#include <cuda_bf16.h>
#include <math.h>
#include <stdint.h>

#define NH    16
#define NKV   8
#define HD    128
#define CEMB  2048
#define BATCH 2
#define TSEQ  2048
#define MROWS (BATCH * TSEQ)
#define KVC   (NKV * HD)   // 1024

// ---------------- scratch ----------------------------------------------------
__device__ float g_qkv[MROWS * 4096];   // per row: q(2048) | k(1024) | v(1024)
__device__ float g_qn [MROWS * CEMB];
__device__ float g_kn [MROWS * KVC];
__device__ float g_ag [MROWS * NH];

__device__ __nv_bfloat16 g_x2   [MROWS * 2 * CEMB];
__device__ __nv_bfloat16 g_y2   [MROWS * 2 * CEMB];   // attention writes this directly
__device__ __nv_bfloat16 g_wqkvt[2 * 4096 * CEMB];
__device__ __nv_bfloat16 g_wpt  [2 * CEMB * CEMB];

// ---------------- helpers ----------------------------------------------------
__device__ __forceinline__ uint32_t smem_u32(const void* p) {
    uint32_t a;
    asm("{ .reg .u64 t; cvta.to.shared.u64 t, %1; cvt.u32.u64 %0, t; }" : "=r"(a) : "l"(p));
    return a;
}
#define CP_ASYNC16(dst, src) \
    asm volatile("cp.async.cg.shared.global [%0], [%1], 16;" :: "r"(dst), "l"(src))
#define CP_COMMIT() asm volatile("cp.async.commit_group;" ::: "memory")
#define CP_WAIT1()  asm volatile("cp.async.wait_group 1;" ::: "memory")

__device__ __forceinline__ void ldm_x4(uint32_t& r0, uint32_t& r1, uint32_t& r2, uint32_t& r3,
                                       uint32_t addr) {
    asm volatile("ldmatrix.sync.aligned.m8n8.x4.shared.b16 {%0,%1,%2,%3}, [%4];"
                 : "=r"(r0), "=r"(r1), "=r"(r2), "=r"(r3) : "r"(addr));
}
__device__ __forceinline__ void mma_bf16(float& d0, float& d1, float& d2, float& d3,
                                         uint32_t a0, uint32_t a1, uint32_t a2, uint32_t a3,
                                         uint32_t b0, uint32_t b1) {
    asm volatile("mma.sync.aligned.m16n8k16.row.col.f32.bf16.bf16.f32 "
                 "{%0,%1,%2,%3}, {%4,%5,%6,%7}, {%8,%9}, {%0,%1,%2,%3};"
                 : "+f"(d0), "+f"(d1), "+f"(d2), "+f"(d3)
                 : "r"(a0), "r"(a1), "r"(a2), "r"(a3), "r"(b0), "r"(b1));
}

// ---------------- packed fp32x2 + fast exp2 ----------------------------------
__device__ __forceinline__ uint64_t pk2(float lo, float hi) {
    float2 f = make_float2(lo, hi);
    return *reinterpret_cast<uint64_t*>(&f);
}
__device__ __forceinline__ float2 upk2(uint64_t u) {
    return *reinterpret_cast<float2*>(&u);
}
__device__ __forceinline__ uint64_t fma2(uint64_t a, uint64_t b, uint64_t c) {
    uint64_t d;
    asm("fma.rn.f32x2 %0, %1, %2, %3;" : "=l"(d) : "l"(a), "l"(b), "l"(c));
    return d;
}
__device__ __forceinline__ float ex2f(float x) {
    float y;
    asm("ex2.approx.f32 %0, %1;" : "=f"(y) : "f"(x));
    return y;
}

// ---------------- fused operand conversion (one launch) ----------------------
__global__ __launch_bounds__(256) void conv_all(
    const float* __restrict__ x,
    const float* __restrict__ wq, const float* __restrict__ wk,
    const float* __restrict__ wv, const float* __restrict__ wproj,
    __nv_bfloat16* __restrict__ x2,
    __nv_bfloat16* __restrict__ wqkvt, __nv_bfloat16* __restrict__ wpt)
{
    const int tid = threadIdx.x;
    if (blockIdx.x < 8192) {
        const int idx = (blockIdx.x * 256 + tid) * 4;
        const int row = idx >> 11;
        const int col = idx & 2047;
        float4 v = *(const float4*)(x + (size_t)row * CEMB + col);
        __nv_bfloat16 h0 = __float2bfloat16(v.x), h1 = __float2bfloat16(v.y);
        __nv_bfloat16 h2 = __float2bfloat16(v.z), h3 = __float2bfloat16(v.w);
        __nv_bfloat16 l0 = __float2bfloat16(v.x - __bfloat162float(h0));
        __nv_bfloat16 l1 = __float2bfloat16(v.y - __bfloat162float(h1));
        __nv_bfloat16 l2 = __float2bfloat16(v.z - __bfloat162float(h2));
        __nv_bfloat16 l3 = __float2bfloat16(v.w - __bfloat162float(h3));
        __nv_bfloat16* base = x2 + (size_t)row * 4096;
        *(__nv_bfloat162*)(base + col)            = __nv_bfloat162(h0, h1);
        *(__nv_bfloat162*)(base + col + 2)        = __nv_bfloat162(h2, h3);
        *(__nv_bfloat162*)(base + 2048 + col)     = __nv_bfloat162(l0, l1);
        *(__nv_bfloat162*)(base + 2048 + col + 2) = __nv_bfloat162(l2, l3);
        return;
    }
    __shared__ float tile[32][33];
    const int fidx = blockIdx.x - 8192;
    const int bx = fidx % 192;
    const int ky = fidx / 192;
    const float* w; __nv_bfloat16* wt;
    int N_src, hib, lob, n0;
    if (bx < 64)       { w = wq;    wt = wqkvt; N_src = 2048; hib = 0;    lob = 4096; n0 = bx * 32; }
    else if (bx < 96)  { w = wk;    wt = wqkvt; N_src = 1024; hib = 2048; lob = 6144; n0 = (bx - 64) * 32; }
    else if (bx < 128) { w = wv;    wt = wqkvt; N_src = 1024; hib = 3072; lob = 7168; n0 = (bx - 96) * 32; }
    else               { w = wproj; wt = wpt;   N_src = 2048; hib = 0;    lob = 2048; n0 = (bx - 128) * 32; }

    const int k0 = ky * 32;
    const int tx = tid & 31, ty = tid >> 5;
#pragma unroll
    for (int r = 0; r < 4; r++)
        tile[ty + 8 * r][tx] = w[(size_t)(k0 + ty + 8 * r) * N_src + n0 + tx];
    __syncthreads();
#pragma unroll
    for (int r = 0; r < 4; r++) {
        const int n = n0 + ty + 8 * r, k = k0 + tx;
        float v = tile[tx][ty + 8 * r];
        __nv_bfloat16 h = __float2bfloat16(v);
        __nv_bfloat16 l = __float2bfloat16(v - __bfloat162float(h));
        wt[(size_t)(hib + n) * CEMB + k] = h;
        wt[(size_t)(lob + n) * CEMB + k] = l;
    }
}

// ---------------- mma.sync split-bf16 GEMM, fused-term single K-pass ----------
// CTA 128x128, BK=32. Stage row (128B) = [hi 64B | lo 64B] for both A and B.
// Per stage: hi/lo fragments loaded once, 3 term-MMAs (hh, lh, hl) share them.
// 3-stage ring = 96KB -> 2 CTAs/SM. 8 warps (4x2), warp tile 32x64.
#define STAGE_BYTES 32768               // A 16KB + B 16KB
#define GSMEM_TOT   (3 * STAGE_BYTES)   // 98304

__global__ __launch_bounds__(256, 2) void mma_gemm(
    const __nv_bfloat16* __restrict__ A2, const __nv_bfloat16* __restrict__ Bt,
    float* __restrict__ C, int N, const float* __restrict__ scale_ptr, int m_base)
{
    extern __shared__ char smem[];
    const uint32_t sb = smem_u32(smem);
    const int tid  = threadIdx.x;
    const int wid  = tid >> 5, lane = tid & 31;
    const int wm   = wid >> 1, wn = wid & 1;
    const int m0   = m_base + blockIdx.y * 128;
    const int n0   = blockIdx.x * 128;

    const int c  = tid & 7;        // chunk: 0-3 = hi halves, 4-7 = lo halves
    const int r0 = tid >> 3;       // 0..31

    const int NIT = 64;            // 2048 / BK32

    const int  ca = c & 3;
    const bool lo = (c >= 4);

    auto load_stage = [&](int i) {
        const int s  = i % 3;
        const int k0 = i * 32;
        const uint32_t da = sb + s * STAGE_BYTES;
        const uint32_t db = da + 16384;
        const __nv_bfloat16* Ap = A2 + (size_t)(m0 + r0) * 4096 + (lo ? 2048 : 0) + k0 + ca * 8;
        const __nv_bfloat16* Bp = Bt + (size_t)((lo ? N : 0) + n0 + r0) * 2048 + k0 + ca * 8;
#pragma unroll
        for (int j = 0; j < 4; j++) {
            const int row = r0 + 32 * j;
            const uint32_t sw = ((c ^ (row & 7)) << 4);
            CP_ASYNC16(da + row * 128 + sw, Ap + (size_t)(32 * j) * 4096);
            CP_ASYNC16(db + row * 128 + sw, Bp + (size_t)(32 * j) * 2048);
        }
        CP_COMMIT();
    };

    const int lrow = lane & 15;
    const int lhi  = lane >> 4;

    int arow[2], brows[4];
#pragma unroll
    for (int mt = 0; mt < 2; mt++) arow[mt]  = wm * 32 + mt * 16 + lrow;
#pragma unroll
    for (int nt = 0; nt < 4; nt++) brows[nt] = wn * 64 + nt * 16 + lrow;

    float acc[2][8][4];
#pragma unroll
    for (int mt = 0; mt < 2; mt++)
#pragma unroll
        for (int j = 0; j < 8; j++)
#pragma unroll
            for (int e = 0; e < 4; e++) acc[mt][j][e] = 0.f;

    load_stage(0);
    load_stage(1);

    for (int i = 0; i < NIT; i++) {
        CP_WAIT1();
        __syncthreads();
        if (i + 2 < NIT) load_stage(i + 2);

        const uint32_t sa = sb + (i % 3) * STAGE_BYTES;
        const uint32_t sB = sa + 16384;

#pragma unroll
        for (int kc = 0; kc < 2; kc++) {
            const int ch = kc * 2 + lhi;      // hi chunk (0..3)
            const int cl = ch + 4;            // lo chunk (4..7)

            uint32_t ah[2][4];
#pragma unroll
            for (int mt = 0; mt < 2; mt++) {
                const int row = arow[mt];
                ldm_x4(ah[mt][0], ah[mt][1], ah[mt][2], ah[mt][3],
                       sa + row * 128 + ((ch ^ (row & 7)) << 4));
            }
            uint32_t bh[4][4];
#pragma unroll
            for (int nt = 0; nt < 4; nt++) {
                const int row = brows[nt];
                ldm_x4(bh[nt][0], bh[nt][1], bh[nt][2], bh[nt][3],
                       sB + row * 128 + ((ch ^ (row & 7)) << 4));
            }
            // term hh: Ahi x Bhi
#pragma unroll
            for (int mt = 0; mt < 2; mt++)
#pragma unroll
                for (int j = 0; j < 8; j++) {
                    const int nt = j >> 1, h = j & 1;
                    mma_bf16(acc[mt][j][0], acc[mt][j][1], acc[mt][j][2], acc[mt][j][3],
                             ah[mt][0], ah[mt][1], ah[mt][2], ah[mt][3],
                             bh[nt][h], bh[nt][h + 2]);
                }
            // term lh: Alo x Bhi (reuse bh)
            uint32_t al[2][4];
#pragma unroll
            for (int mt = 0; mt < 2; mt++) {
                const int row = arow[mt];
                ldm_x4(al[mt][0], al[mt][1], al[mt][2], al[mt][3],
                       sa + row * 128 + ((cl ^ (row & 7)) << 4));
            }
#pragma unroll
            for (int mt = 0; mt < 2; mt++)
#pragma unroll
                for (int j = 0; j < 8; j++) {
                    const int nt = j >> 1, h = j & 1;
                    mma_bf16(acc[mt][j][0], acc[mt][j][1], acc[mt][j][2], acc[mt][j][3],
                             al[mt][0], al[mt][1], al[mt][2], al[mt][3],
                             bh[nt][h], bh[nt][h + 2]);
                }
            // term hl: Ahi x Blo (reuse ah)
            uint32_t bl[4][4];
#pragma unroll
            for (int nt = 0; nt < 4; nt++) {
                const int row = brows[nt];
                ldm_x4(bl[nt][0], bl[nt][1], bl[nt][2], bl[nt][3],
                       sB + row * 128 + ((cl ^ (row & 7)) << 4));
            }
#pragma unroll
            for (int mt = 0; mt < 2; mt++)
#pragma unroll
                for (int j = 0; j < 8; j++) {
                    const int nt = j >> 1, h = j & 1;
                    mma_bf16(acc[mt][j][0], acc[mt][j][1], acc[mt][j][2], acc[mt][j][3],
                             ah[mt][0], ah[mt][1], ah[mt][2], ah[mt][3],
                             bl[nt][h], bl[nt][h + 2]);
                }
        }
    }

    const float sc = scale_ptr ? (1.0f + scale_ptr[0]) : 1.0f;
#pragma unroll
    for (int mt = 0; mt < 2; mt++) {
        const int r = m0 + wm * 32 + mt * 16 + (lane >> 2);
#pragma unroll
        for (int j = 0; j < 8; j++) {
            const int cb = n0 + wn * 64 + j * 8 + 2 * (lane & 3);
            float2 v0 = make_float2(acc[mt][j][0] * sc, acc[mt][j][1] * sc);
            float2 v1 = make_float2(acc[mt][j][2] * sc, acc[mt][j][3] * sc);
            *(float2*)(C + (size_t)r * N + cb)       = v0;
            *(float2*)(C + (size_t)(r + 8) * N + cb) = v1;
        }
    }
}

// ---------------- fused prep: gates (v update + attn gate) + rope/rmsnorm ----
__global__ __launch_bounds__(128) void prep_kernel(
    const float* __restrict__ x, const float* __restrict__ ve,
    const float* __restrict__ wvg, const float* __restrict__ wag,
    const float* __restrict__ cosb, const float* __restrict__ sinb)
{
    const int tid = threadIdx.x;
    if (blockIdx.x < MROWS) {
        const int bt = blockIdx.x;
        __shared__ float xs[32];
        __shared__ float sg[8];

        if (tid < 32) xs[tid] = x[(size_t)bt * CEMB + tid];
        __syncthreads();

        if (tid < 8) {
            float s = 0.f;
#pragma unroll
            for (int c = 0; c < 32; c++) s += xs[c] * wvg[c * 8 + tid];
            sg[tid] = 2.0f / (1.0f + __expf(-s));
        } else if (tid >= 32 && tid < 48) {
            int h = tid - 32;
            float s = 0.f;
#pragma unroll
            for (int c = 0; c < 12; c++) s += xs[c] * wag[c * 16 + h];
            g_ag[(size_t)bt * NH + h] = 1.0f / (1.0f + __expf(-s));
        }
        __syncthreads();

        for (int i = tid; i < KVC; i += 128)
            g_qkv[(size_t)bt * 4096 + 3072 + i] += sg[i >> 7] * ve[(size_t)bt * KVC + i];
    } else {
        const int gw   = (blockIdx.x - MROWS) * 4 + (tid >> 5);
        const int lane = tid & 31;
        const int bt = gw / 24;
        const int hh = gw % 24;
        const int t  = bt % TSEQ;

        const float c0 = cosb[t * 64 + lane];
        const float c1 = cosb[t * 64 + lane + 32];
        const float s0 = sinb[t * 64 + lane];
        const float s1 = sinb[t * 64 + lane + 32];

        float t1a, t1b, t2a, t2b;
        float* dst;
        if (hh < 16) {
            const float* base = g_qkv + (size_t)bt * 4096 + hh * HD;
            t1a = base[lane];      t1b = base[lane + 32];
            t2a = base[64 + lane]; t2b = base[96 + lane];
            dst = g_qn + (size_t)bt * CEMB + hh * HD;
        } else {
            const int j = hh - 16;
            const float* base = g_qkv + (size_t)bt * 4096 + 2048 + j * HD;
            const int bt2 = (t == 0) ? bt : (bt - 1);
            const float* base2 = g_qkv + (size_t)bt2 * 4096 + 2048 + j * HD;
            t1a = base [lane];      t1b = base [lane + 32];
            t2a = base2[64 + lane]; t2b = base2[96 + lane];
            dst = g_kn + (size_t)bt * KVC + j * HD;
        }

        float o1a =  t1a * c0 + t2a * s0;
        float o1b =  t1b * c1 + t2b * s1;
        float o2a = -t1a * s0 + t2a * c0;
        float o2b = -t1b * s1 + t2b * c1;

        float ss = o1a * o1a + o1b * o1b + o2a * o2a + o2b * o2b;
#pragma unroll
        for (int o = 16; o > 0; o >>= 1) ss += __shfl_xor_sync(0xffffffffu, ss, o);
        const float r = rsqrtf(ss * (1.0f / 128.0f) + 1.1920929e-7f);

        dst[lane]      = o1a * r;
        dst[lane + 32] = o1b * r;
        dst[64 + lane] = o2a * r;
        dst[96 + lane] = o2b * r;
    }
}

// ---------------- branchless attention: 4 q-rows/thread, 16 dims/thread -------
// (R11-proven shape: static smem, conflict-free 20-float group stride)
#define KROW 160

__global__ __launch_bounds__(256, 1) void attn_kernel(const int* __restrict__ wsp)
{
    __shared__ __align__(16) float Ksm[32 * KROW];
    __shared__ __align__(16) float Vsm[32 * KROW];

    const int tile = blockIdx.x;
    const int bh   = blockIdx.y;
    const int b = bh / NH, h = bh % NH;
    const int kvh = h >> 1;
    const int tid = threadIdx.x;
    const int rowg = tid >> 3;
    const int oct  = tid & 7;
    const int q0   = tile * 128;

    int WS = wsp[0];
    if (WS <= 0 || WS > (1 << 20)) WS = 1024;
    const float QS = 0.088388347648318447f * 1.4426950408889634f;
    const float M2 = 16.33f;

    int qi[4];
#pragma unroll
    for (int r = 0; r < 4; r++) qi[r] = q0 + rowg * 4 + r;

    const int wq_lo = q0 + ((tid >> 5) << 4);
    const int wq_hi = wq_lo + 15;

    uint64_t q2[4][8];
#pragma unroll
    for (int r = 0; r < 4; r++) {
        const float* qp = g_qn + (size_t)(b * TSEQ + qi[r]) * CEMB + h * HD + oct * 16;
#pragma unroll
        for (int i = 0; i < 4; i++) {
            float4 v = *(const float4*)(qp + 4 * i);
            q2[r][2 * i]     = pk2(v.x * QS, v.y * QS);
            q2[r][2 * i + 1] = pk2(v.z * QS, v.w * QS);
        }
    }

    uint64_t acc[4][8];
#pragma unroll
    for (int r = 0; r < 4; r++)
#pragma unroll
        for (int i = 0; i < 8; i++) acc[r][i] = 0ull;
    float lsum[4] = {0.f, 0.f, 0.f, 0.f};

    int kmin = q0 - WS; if (kmin < 0) kmin = 0;
    const int kt0 = kmin & ~31;

    for (int kt = kt0; kt <= q0 + 127; kt += 32) {
        __syncthreads();
        {
            const float* Kb = g_kn  + (size_t)(b * TSEQ + kt) * KVC + kvh * HD;
            const float* Vb = g_qkv + (size_t)(b * TSEQ + kt) * 4096 + 3072 + kvh * HD;
#pragma unroll
            for (int i = 0; i < 4; i++) {
                const int f   = i * 256 + tid;
                const int r   = f >> 5;
                const int c4  = f & 31;
                const int dst = r * KROW + (c4 >> 2) * 20 + (c4 & 3) * 4;
                *(float4*)(Ksm + dst) = *(const float4*)(Kb + (size_t)r * KVC  + c4 * 4);
                *(float4*)(Vsm + dst) = *(const float4*)(Vb + (size_t)r * 4096 + c4 * 4);
            }
        }
        __syncthreads();

        if (kt > wq_hi || kt + 31 < wq_lo - WS) continue;

#pragma unroll 1
        for (int j0 = 0; j0 < 32; j0 += 4) {
            float sv[4][4];
#pragma unroll
            for (int jj = 0; jj < 4; jj++) {
                const float4* kr4 = (const float4*)(Ksm + (j0 + jj) * KROW + oct * 20);
                float4 k0 = kr4[0], k1 = kr4[1], k2 = kr4[2], k3 = kr4[3];
                const uint64_t kp0 = pk2(k0.x, k0.y), kp1 = pk2(k0.z, k0.w);
                const uint64_t kp2 = pk2(k1.x, k1.y), kp3 = pk2(k1.z, k1.w);
                const uint64_t kp4 = pk2(k2.x, k2.y), kp5 = pk2(k2.z, k2.w);
                const uint64_t kp6 = pk2(k3.x, k3.y), kp7 = pk2(k3.z, k3.w);
#pragma unroll
                for (int r = 0; r < 4; r++) {
                    uint64_t d0 = 0ull, d1 = 0ull;
                    d0 = fma2(q2[r][0], kp0, d0);
                    d1 = fma2(q2[r][1], kp1, d1);
                    d0 = fma2(q2[r][2], kp2, d0);
                    d1 = fma2(q2[r][3], kp3, d1);
                    d0 = fma2(q2[r][4], kp4, d0);
                    d1 = fma2(q2[r][5], kp5, d1);
                    d0 = fma2(q2[r][6], kp6, d0);
                    d1 = fma2(q2[r][7], kp7, d1);
                    float2 e0 = upk2(d0), e1 = upk2(d1);
                    sv[jj][r] = (e0.x + e0.y) + (e1.x + e1.y);
                }
            }
#pragma unroll
            for (int jj = 0; jj < 4; jj++)
#pragma unroll
                for (int r = 0; r < 4; r++)
                    sv[jj][r] += __shfl_xor_sync(0xffffffffu, sv[jj][r], 1);
#pragma unroll
            for (int jj = 0; jj < 4; jj++)
#pragma unroll
                for (int r = 0; r < 4; r++)
                    sv[jj][r] += __shfl_xor_sync(0xffffffffu, sv[jj][r], 2);
#pragma unroll
            for (int jj = 0; jj < 4; jj++)
#pragma unroll
                for (int r = 0; r < 4; r++)
                    sv[jj][r] += __shfl_xor_sync(0xffffffffu, sv[jj][r], 4);

            float pv[4][4];
#pragma unroll
            for (int jj = 0; jj < 4; jj++)
#pragma unroll
                for (int r = 0; r < 4; r++) {
                    const int kj = kt + j0 + jj;
                    const bool valid = (kj <= qi[r]) && (kj >= qi[r] - WS);
                    const float e = ex2f(sv[jj][r] - M2);
                    pv[jj][r] = valid ? e : 0.f;
                    lsum[r] += pv[jj][r];
                }

#pragma unroll
            for (int jj = 0; jj < 4; jj++) {
                const float4* vr4 = (const float4*)(Vsm + (j0 + jj) * KROW + oct * 20);
                float4 v0 = vr4[0], v1 = vr4[1], v2 = vr4[2], v3 = vr4[3];
                const uint64_t vp0 = pk2(v0.x, v0.y), vp1 = pk2(v0.z, v0.w);
                const uint64_t vp2 = pk2(v1.x, v1.y), vp3 = pk2(v1.z, v1.w);
                const uint64_t vp4 = pk2(v2.x, v2.y), vp5 = pk2(v2.z, v2.w);
                const uint64_t vp6 = pk2(v3.x, v3.y), vp7 = pk2(v3.z, v3.w);
#pragma unroll
                for (int r = 0; r < 4; r++) {
                    const uint64_t pp = pk2(pv[jj][r], pv[jj][r]);
                    acc[r][0] = fma2(pp, vp0, acc[r][0]);
                    acc[r][1] = fma2(pp, vp1, acc[r][1]);
                    acc[r][2] = fma2(pp, vp2, acc[r][2]);
                    acc[r][3] = fma2(pp, vp3, acc[r][3]);
                    acc[r][4] = fma2(pp, vp4, acc[r][4]);
                    acc[r][5] = fma2(pp, vp5, acc[r][5]);
                    acc[r][6] = fma2(pp, vp6, acc[r][6]);
                    acc[r][7] = fma2(pp, vp7, acc[r][7]);
                }
            }
        }
    }

#pragma unroll
    for (int r = 0; r < 4; r++) {
        const float ag  = g_ag[(size_t)(b * TSEQ + qi[r]) * NH + h];
        const float inv = ag / lsum[r];
        __nv_bfloat16* base = g_y2 + (size_t)(b * TSEQ + qi[r]) * 4096 + h * HD + oct * 16;
#pragma unroll
        for (int i = 0; i < 8; i++) {
            float2 a = upk2(acc[r][i]);
            const float f0 = a.x * inv, f1 = a.y * inv;
            __nv_bfloat16 h0 = __float2bfloat16(f0);
            __nv_bfloat16 h1 = __float2bfloat16(f1);
            __nv_bfloat16 l0 = __float2bfloat16(f0 - __bfloat162float(h0));
            __nv_bfloat16 l1 = __float2bfloat16(f1 - __bfloat162float(h1));
            *(__nv_bfloat162*)(base + 2 * i)        = __nv_bfloat162(h0, h1);
            *(__nv_bfloat162*)(base + 2048 + 2 * i) = __nv_bfloat162(l0, l1);
        }
    }
}

// ---------------- launcher ---------------------------------------------------
extern "C" void kernel_launch(void* const* d_in, const int* in_sizes, int n_in,
                              void* d_out, int out_size)
{
    const float* x     = (const float*)d_in[0];
    const float* ve    = (const float*)d_in[1];
    const float* cosb  = (const float*)d_in[2];
    const float* sinb  = (const float*)d_in[3];
    const float* wq    = (const float*)d_in[4];
    const float* wk    = (const float*)d_in[5];
    const float* wv    = (const float*)d_in[6];
    const float* wproj = (const float*)d_in[7];
    const float* wvg   = (const float*)d_in[8];
    const float* wag   = (const float*)d_in[9];
    const float* ps    = (const float*)d_in[10];
    const int*   wsp   = (const int*)  d_in[11];
    float* out = (float*)d_out;

    float *pqkv;
    __nv_bfloat16 *px2, *py2, *pwqkvt, *pwpt;
    cudaGetSymbolAddress((void**)&pqkv,   g_qkv);
    cudaGetSymbolAddress((void**)&px2,    g_x2);
    cudaGetSymbolAddress((void**)&py2,    g_y2);
    cudaGetSymbolAddress((void**)&pwqkvt, g_wqkvt);
    cudaGetSymbolAddress((void**)&pwpt,   g_wpt);

    cudaFuncSetAttribute(mma_gemm, cudaFuncAttributeMaxDynamicSharedMemorySize, GSMEM_TOT);

    // 1: all operand conversions in one launch
    conv_all<<<20480, 256>>>(x, wq, wk, wv, wproj, px2, pwqkvt, pwpt);
    // 2: fused QKV projection (N=4096)
    mma_gemm<<<dim3(32, MROWS / 128), 256, GSMEM_TOT>>>(px2, pwqkvt, pqkv, 4096, nullptr, 0);
    // 3: fused gates + rope/rmsnorm
    prep_kernel<<<MROWS + MROWS * 24 / 4, 128>>>(x, ve, wvg, wag, cosb, sinb);
    // 4: attention — writes split-bf16 y directly
    attn_kernel<<<dim3(TSEQ / 128, BATCH * NH), 256>>>(wsp);
    // 5: output projection
    mma_gemm<<<dim3(16, MROWS / 128), 256, GSMEM_TOT>>>(py2, pwpt, out, CEMB, ps, 0);
}

// round 15
// speedup vs baseline: 1.0891x; 1.0343x over previous
#include <cuda_runtime.h>
#include <cuda_bf16.h>
#include <math.h>
#include <stdint.h>

#define NH    16
#define NKV   8
#define HD    128
#define CEMB  2048
#define BATCH 2
#define TSEQ  2048
#define MROWS (BATCH * TSEQ)
#define KVC   (NKV * HD)   // 1024

// ---------------- scratch ----------------------------------------------------
__device__ float g_qkv[MROWS * 4096];   // per row: q(2048) | k(1024) | v(1024)
__device__ float g_qn [MROWS * CEMB];
__device__ float g_kn [MROWS * KVC];
__device__ float g_ag [MROWS * NH];

__device__ __nv_bfloat16 g_x2   [MROWS * 2 * CEMB];
__device__ __nv_bfloat16 g_y2   [MROWS * 2 * CEMB];   // attention writes this directly
__device__ __nv_bfloat16 g_wqkvt[2 * 4096 * CEMB];
__device__ __nv_bfloat16 g_wpt  [2 * CEMB * CEMB];

// ---------------- helpers ----------------------------------------------------
__device__ __forceinline__ uint32_t smem_u32(const void* p) {
    uint32_t a;
    asm("{ .reg .u64 t; cvta.to.shared.u64 t, %1; cvt.u32.u64 %0, t; }" : "=r"(a) : "l"(p));
    return a;
}
#define CP_ASYNC16(dst, src) \
    asm volatile("cp.async.cg.shared.global [%0], [%1], 16;" :: "r"(dst), "l"(src))
#define CP_COMMIT() asm volatile("cp.async.commit_group;" ::: "memory")
#define CP_WAIT1()  asm volatile("cp.async.wait_group 1;" ::: "memory")
#define CP_WAIT0()  asm volatile("cp.async.wait_group 0;" ::: "memory")

__device__ __forceinline__ void ldm_x4(uint32_t& r0, uint32_t& r1, uint32_t& r2, uint32_t& r3,
                                       uint32_t addr) {
    asm volatile("ldmatrix.sync.aligned.m8n8.x4.shared.b16 {%0,%1,%2,%3}, [%4];"
                 : "=r"(r0), "=r"(r1), "=r"(r2), "=r"(r3) : "r"(addr));
}
__device__ __forceinline__ void mma_bf16(float& d0, float& d1, float& d2, float& d3,
                                         uint32_t a0, uint32_t a1, uint32_t a2, uint32_t a3,
                                         uint32_t b0, uint32_t b1) {
    asm volatile("mma.sync.aligned.m16n8k16.row.col.f32.bf16.bf16.f32 "
                 "{%0,%1,%2,%3}, {%4,%5,%6,%7}, {%8,%9}, {%0,%1,%2,%3};"
                 : "+f"(d0), "+f"(d1), "+f"(d2), "+f"(d3)
                 : "r"(a0), "r"(a1), "r"(a2), "r"(a3), "r"(b0), "r"(b1));
}

// ---------------- packed fp32x2 + fast exp2 ----------------------------------
__device__ __forceinline__ uint64_t pk2(float lo, float hi) {
    float2 f = make_float2(lo, hi);
    return *reinterpret_cast<uint64_t*>(&f);
}
__device__ __forceinline__ float2 upk2(uint64_t u) {
    return *reinterpret_cast<float2*>(&u);
}
__device__ __forceinline__ uint64_t fma2(uint64_t a, uint64_t b, uint64_t c) {
    uint64_t d;
    asm("fma.rn.f32x2 %0, %1, %2, %3;" : "=l"(d) : "l"(a), "l"(b), "l"(c));
    return d;
}
__device__ __forceinline__ float ex2f(float x) {
    float y;
    asm("ex2.approx.f32 %0, %1;" : "=f"(y) : "f"(x));
    return y;
}

// ---------------- fused operand conversion (one launch) ----------------------
__global__ __launch_bounds__(256) void conv_all(
    const float* __restrict__ x,
    const float* __restrict__ wq, const float* __restrict__ wk,
    const float* __restrict__ wv, const float* __restrict__ wproj,
    __nv_bfloat16* __restrict__ x2,
    __nv_bfloat16* __restrict__ wqkvt, __nv_bfloat16* __restrict__ wpt)
{
    const int tid = threadIdx.x;
    if (blockIdx.x < 8192) {
        const int idx = (blockIdx.x * 256 + tid) * 4;
        const int row = idx >> 11;
        const int col = idx & 2047;
        float4 v = *(const float4*)(x + (size_t)row * CEMB + col);
        __nv_bfloat16 h0 = __float2bfloat16(v.x), h1 = __float2bfloat16(v.y);
        __nv_bfloat16 h2 = __float2bfloat16(v.z), h3 = __float2bfloat16(v.w);
        __nv_bfloat16 l0 = __float2bfloat16(v.x - __bfloat162float(h0));
        __nv_bfloat16 l1 = __float2bfloat16(v.y - __bfloat162float(h1));
        __nv_bfloat16 l2 = __float2bfloat16(v.z - __bfloat162float(h2));
        __nv_bfloat16 l3 = __float2bfloat16(v.w - __bfloat162float(h3));
        __nv_bfloat16* base = x2 + (size_t)row * 4096;
        *(__nv_bfloat162*)(base + col)            = __nv_bfloat162(h0, h1);
        *(__nv_bfloat162*)(base + col + 2)        = __nv_bfloat162(h2, h3);
        *(__nv_bfloat162*)(base + 2048 + col)     = __nv_bfloat162(l0, l1);
        *(__nv_bfloat162*)(base + 2048 + col + 2) = __nv_bfloat162(l2, l3);
        return;
    }
    __shared__ float tile[32][33];
    const int fidx = blockIdx.x - 8192;
    const int bx = fidx % 192;
    const int ky = fidx / 192;
    const float* w; __nv_bfloat16* wt;
    int N_src, hib, lob, n0;
    if (bx < 64)       { w = wq;    wt = wqkvt; N_src = 2048; hib = 0;    lob = 4096; n0 = bx * 32; }
    else if (bx < 96)  { w = wk;    wt = wqkvt; N_src = 1024; hib = 2048; lob = 6144; n0 = (bx - 64) * 32; }
    else if (bx < 128) { w = wv;    wt = wqkvt; N_src = 1024; hib = 3072; lob = 7168; n0 = (bx - 96) * 32; }
    else               { w = wproj; wt = wpt;   N_src = 2048; hib = 0;    lob = 2048; n0 = (bx - 128) * 32; }

    const int k0 = ky * 32;
    const int tx = tid & 31, ty = tid >> 5;
#pragma unroll
    for (int r = 0; r < 4; r++)
        tile[ty + 8 * r][tx] = w[(size_t)(k0 + ty + 8 * r) * N_src + n0 + tx];
    __syncthreads();
#pragma unroll
    for (int r = 0; r < 4; r++) {
        const int n = n0 + ty + 8 * r, k = k0 + tx;
        float v = tile[tx][ty + 8 * r];
        __nv_bfloat16 h = __float2bfloat16(v);
        __nv_bfloat16 l = __float2bfloat16(v - __bfloat162float(h));
        wt[(size_t)(hib + n) * CEMB + k] = h;
        wt[(size_t)(lob + n) * CEMB + k] = l;
    }
}

// ---------------- mma.sync split-bf16 GEMM, two-phase fused ------------------
// Phase 1 (hh + lh): BK=64, 2-stage 48KB (A rows 256B = hi|lo, B-hi 128B rows).
//   Per kk: 8 LDSM : 32 MMA. Live frags acc64+bh16+ah8+al8 ~= 96 -> no spill.
// Phase 2 (hl): BK=64, 2-stage 32KB, A-hi x B-lo, per kk 6 LDSM : 16 MMA.
// Total LDSM -22%, L2 stage traffic -17% vs 3-pass. 96KB -> 2 CTAs/SM.
#define P1_STAGE 49152
#define P2_STAGE 32768
#define GSMEM_TOT (2 * P1_STAGE)   // 98304

__global__ __launch_bounds__(256, 2) void mma_gemm(
    const __nv_bfloat16* __restrict__ A2, const __nv_bfloat16* __restrict__ Bt,
    float* __restrict__ C, int N, const float* __restrict__ scale_ptr, int m_base)
{
    extern __shared__ char smem[];
    const uint32_t sb = smem_u32(smem);
    const int tid  = threadIdx.x;
    const int wid  = tid >> 5, lane = tid & 31;
    const int wm   = wid >> 1, wn = wid & 1;
    const int m0   = m_base + blockIdx.y * 128;
    const int n0   = blockIdx.x * 128;

    const int c  = tid & 7;
    const int r0 = tid >> 3;

    const int lrow = lane & 15;
    const int lhi  = lane >> 4;

    int arow[2], brows[4];
#pragma unroll
    for (int mt = 0; mt < 2; mt++) arow[mt]  = wm * 32 + mt * 16 + lrow;
#pragma unroll
    for (int nt = 0; nt < 4; nt++) brows[nt] = wn * 64 + nt * 16 + lrow;

    float acc[2][8][4];
#pragma unroll
    for (int mt = 0; mt < 2; mt++)
#pragma unroll
        for (int j = 0; j < 8; j++)
#pragma unroll
            for (int e = 0; e < 4; e++) acc[mt][j][e] = 0.f;

    // ---------------- phase 1: acc += Ahi*Bhi + Alo*Bhi ----------------
    auto load1 = [&](int i) {
        const int s  = i & 1;
        const int k0 = i * 64;
        const uint32_t da = sb + s * P1_STAGE;
        const uint32_t db = da + 32768;
        const __nv_bfloat16* Ap = A2 + (size_t)(m0 + r0) * 4096 + k0 + c * 8;
        const __nv_bfloat16* Bp = Bt + (size_t)(n0 + r0) * 2048 + k0 + c * 8;
#pragma unroll
        for (int j = 0; j < 4; j++) {
            const int row = r0 + 32 * j;
            const uint32_t sw = ((c ^ (row & 7)) << 4);
            CP_ASYNC16(da + row * 256 + sw,       Ap + (size_t)(32 * j) * 4096);
            CP_ASYNC16(da + row * 256 + 128 + sw, Ap + (size_t)(32 * j) * 4096 + 2048);
            CP_ASYNC16(db + row * 128 + sw,       Bp + (size_t)(32 * j) * 2048);
        }
        CP_COMMIT();
    };

    load1(0);
    for (int i = 0; i < 32; i++) {
        __syncthreads();                      // prev compute done; buffer (i+1)&1 free
        if (i + 1 < 32) { load1(i + 1); CP_WAIT1(); }
        else            { CP_WAIT0(); }
        __syncthreads();                      // tile i visible to all

        const uint32_t sa = sb + (i & 1) * P1_STAGE;
        const uint32_t sB = sa + 32768;

#pragma unroll
        for (int kk = 0; kk < 4; kk++) {
            const int chunk = kk * 2 + lhi;
            uint32_t bh[4][4];
#pragma unroll
            for (int nt = 0; nt < 4; nt++) {
                const int row = brows[nt];
                ldm_x4(bh[nt][0], bh[nt][1], bh[nt][2], bh[nt][3],
                       sB + row * 128 + ((chunk ^ (row & 7)) << 4));
            }
            uint32_t ah[2][4];
#pragma unroll
            for (int mt = 0; mt < 2; mt++) {
                const int row = arow[mt];
                ldm_x4(ah[mt][0], ah[mt][1], ah[mt][2], ah[mt][3],
                       sa + row * 256 + ((chunk ^ (row & 7)) << 4));
            }
#pragma unroll
            for (int mt = 0; mt < 2; mt++)
#pragma unroll
                for (int j = 0; j < 8; j++) {
                    const int nt = j >> 1, h = j & 1;
                    mma_bf16(acc[mt][j][0], acc[mt][j][1], acc[mt][j][2], acc[mt][j][3],
                             ah[mt][0], ah[mt][1], ah[mt][2], ah[mt][3],
                             bh[nt][h], bh[nt][h + 2]);
                }
            uint32_t al[2][4];
#pragma unroll
            for (int mt = 0; mt < 2; mt++) {
                const int row = arow[mt];
                ldm_x4(al[mt][0], al[mt][1], al[mt][2], al[mt][3],
                       sa + row * 256 + 128 + ((chunk ^ (row & 7)) << 4));
            }
#pragma unroll
            for (int mt = 0; mt < 2; mt++)
#pragma unroll
                for (int j = 0; j < 8; j++) {
                    const int nt = j >> 1, h = j & 1;
                    mma_bf16(acc[mt][j][0], acc[mt][j][1], acc[mt][j][2], acc[mt][j][3],
                             al[mt][0], al[mt][1], al[mt][2], al[mt][3],
                             bh[nt][h], bh[nt][h + 2]);
                }
        }
    }

    __syncthreads();    // all phase-1 smem reads done before phase-2 overwrites

    // ---------------- phase 2: acc += Ahi*Blo ----------------
    auto load2 = [&](int i) {
        const int s  = i & 1;
        const int k0 = i * 64;
        const uint32_t da = sb + s * P2_STAGE;
        const uint32_t db = da + 16384;
        const __nv_bfloat16* Ap = A2 + (size_t)(m0 + r0) * 4096 + k0 + c * 8;            // hi
        const __nv_bfloat16* Bp = Bt + (size_t)(N + n0 + r0) * 2048 + k0 + c * 8;        // lo
#pragma unroll
        for (int j = 0; j < 4; j++) {
            const int row = r0 + 32 * j;
            const uint32_t sw = ((c ^ (row & 7)) << 4);
            CP_ASYNC16(da + row * 128 + sw, Ap + (size_t)(32 * j) * 4096);
            CP_ASYNC16(db + row * 128 + sw, Bp + (size_t)(32 * j) * 2048);
        }
        CP_COMMIT();
    };

    load2(0);
    for (int i = 0; i < 32; i++) {
        __syncthreads();
        if (i + 1 < 32) { load2(i + 1); CP_WAIT1(); }
        else            { CP_WAIT0(); }
        __syncthreads();

        const uint32_t sa = sb + (i & 1) * P2_STAGE;
        const uint32_t sB = sa + 16384;

#pragma unroll
        for (int kk = 0; kk < 4; kk++) {
            const int chunk = kk * 2 + lhi;
            uint32_t a[2][4];
#pragma unroll
            for (int mt = 0; mt < 2; mt++) {
                const int row = arow[mt];
                ldm_x4(a[mt][0], a[mt][1], a[mt][2], a[mt][3],
                       sa + row * 128 + ((chunk ^ (row & 7)) << 4));
            }
            uint32_t bt[4][4];
#pragma unroll
            for (int nt = 0; nt < 4; nt++) {
                const int row = brows[nt];
                ldm_x4(bt[nt][0], bt[nt][1], bt[nt][2], bt[nt][3],
                       sB + row * 128 + ((chunk ^ (row & 7)) << 4));
            }
#pragma unroll
            for (int mt = 0; mt < 2; mt++)
#pragma unroll
                for (int j = 0; j < 8; j++) {
                    const int nt = j >> 1, h = j & 1;
                    mma_bf16(acc[mt][j][0], acc[mt][j][1], acc[mt][j][2], acc[mt][j][3],
                             a[mt][0], a[mt][1], a[mt][2], a[mt][3],
                             bt[nt][h], bt[nt][h + 2]);
                }
        }
    }

    const float sc = scale_ptr ? (1.0f + scale_ptr[0]) : 1.0f;
#pragma unroll
    for (int mt = 0; mt < 2; mt++) {
        const int r = m0 + wm * 32 + mt * 16 + (lane >> 2);
#pragma unroll
        for (int j = 0; j < 8; j++) {
            const int cb = n0 + wn * 64 + j * 8 + 2 * (lane & 3);
            float2 v0 = make_float2(acc[mt][j][0] * sc, acc[mt][j][1] * sc);
            float2 v1 = make_float2(acc[mt][j][2] * sc, acc[mt][j][3] * sc);
            *(float2*)(C + (size_t)r * N + cb)       = v0;
            *(float2*)(C + (size_t)(r + 8) * N + cb) = v1;
        }
    }
}

// ---------------- fused prep: gates (v update + attn gate) + rope/rmsnorm ----
__global__ __launch_bounds__(128) void prep_kernel(
    const float* __restrict__ x, const float* __restrict__ ve,
    const float* __restrict__ wvg, const float* __restrict__ wag,
    const float* __restrict__ cosb, const float* __restrict__ sinb)
{
    const int tid = threadIdx.x;
    if (blockIdx.x < MROWS) {
        const int bt = blockIdx.x;
        __shared__ float xs[32];
        __shared__ float sg[8];

        if (tid < 32) xs[tid] = x[(size_t)bt * CEMB + tid];
        __syncthreads();

        if (tid < 8) {
            float s = 0.f;
#pragma unroll
            for (int c = 0; c < 32; c++) s += xs[c] * wvg[c * 8 + tid];
            sg[tid] = 2.0f / (1.0f + __expf(-s));
        } else if (tid >= 32 && tid < 48) {
            int h = tid - 32;
            float s = 0.f;
#pragma unroll
            for (int c = 0; c < 12; c++) s += xs[c] * wag[c * 16 + h];
            g_ag[(size_t)bt * NH + h] = 1.0f / (1.0f + __expf(-s));
        }
        __syncthreads();

        for (int i = tid; i < KVC; i += 128)
            g_qkv[(size_t)bt * 4096 + 3072 + i] += sg[i >> 7] * ve[(size_t)bt * KVC + i];
    } else {
        const int gw   = (blockIdx.x - MROWS) * 4 + (tid >> 5);
        const int lane = tid & 31;
        const int bt = gw / 24;
        const int hh = gw % 24;
        const int t  = bt % TSEQ;

        const float c0 = cosb[t * 64 + lane];
        const float c1 = cosb[t * 64 + lane + 32];
        const float s0 = sinb[t * 64 + lane];
        const float s1 = sinb[t * 64 + lane + 32];

        float t1a, t1b, t2a, t2b;
        float* dst;
        if (hh < 16) {
            const float* base = g_qkv + (size_t)bt * 4096 + hh * HD;
            t1a = base[lane];      t1b = base[lane + 32];
            t2a = base[64 + lane]; t2b = base[96 + lane];
            dst = g_qn + (size_t)bt * CEMB + hh * HD;
        } else {
            const int j = hh - 16;
            const float* base = g_qkv + (size_t)bt * 4096 + 2048 + j * HD;
            const int bt2 = (t == 0) ? bt : (bt - 1);
            const float* base2 = g_qkv + (size_t)bt2 * 4096 + 2048 + j * HD;
            t1a = base [lane];      t1b = base [lane + 32];
            t2a = base2[64 + lane]; t2b = base2[96 + lane];
            dst = g_kn + (size_t)bt * KVC + j * HD;
        }

        float o1a =  t1a * c0 + t2a * s0;
        float o1b =  t1b * c1 + t2b * s1;
        float o2a = -t1a * s0 + t2a * c0;
        float o2b = -t1b * s1 + t2b * c1;

        float ss = o1a * o1a + o1b * o1b + o2a * o2a + o2b * o2b;
#pragma unroll
        for (int o = 16; o > 0; o >>= 1) ss += __shfl_xor_sync(0xffffffffu, ss, o);
        const float r = rsqrtf(ss * (1.0f / 128.0f) + 1.1920929e-7f);

        dst[lane]      = o1a * r;
        dst[lane + 32] = o1b * r;
        dst[64 + lane] = o2a * r;
        dst[96 + lane] = o2b * r;
    }
}

// ---------------- branchless attention: 4 q-rows/thread, 16 dims/thread -------
// (R11-proven shape: static smem, conflict-free 20-float group stride)
#define KROW 160

__global__ __launch_bounds__(256, 1) void attn_kernel(const int* __restrict__ wsp)
{
    __shared__ __align__(16) float Ksm[32 * KROW];
    __shared__ __align__(16) float Vsm[32 * KROW];

    const int tile = blockIdx.x;
    const int bh   = blockIdx.y;
    const int b = bh / NH, h = bh % NH;
    const int kvh = h >> 1;
    const int tid = threadIdx.x;
    const int rowg = tid >> 3;
    const int oct  = tid & 7;
    const int q0   = tile * 128;

    int WS = wsp[0];
    if (WS <= 0 || WS > (1 << 20)) WS = 1024;
    const float QS = 0.088388347648318447f * 1.4426950408889634f;
    const float M2 = 16.33f;

    int qi[4];
#pragma unroll
    for (int r = 0; r < 4; r++) qi[r] = q0 + rowg * 4 + r;

    const int wq_lo = q0 + ((tid >> 5) << 4);
    const int wq_hi = wq_lo + 15;

    uint64_t q2[4][8];
#pragma unroll
    for (int r = 0; r < 4; r++) {
        const float* qp = g_qn + (size_t)(b * TSEQ + qi[r]) * CEMB + h * HD + oct * 16;
#pragma unroll
        for (int i = 0; i < 4; i++) {
            float4 v = *(const float4*)(qp + 4 * i);
            q2[r][2 * i]     = pk2(v.x * QS, v.y * QS);
            q2[r][2 * i + 1] = pk2(v.z * QS, v.w * QS);
        }
    }

    uint64_t acc[4][8];
#pragma unroll
    for (int r = 0; r < 4; r++)
#pragma unroll
        for (int i = 0; i < 8; i++) acc[r][i] = 0ull;
    float lsum[4] = {0.f, 0.f, 0.f, 0.f};

    int kmin = q0 - WS; if (kmin < 0) kmin = 0;
    const int kt0 = kmin & ~31;

    for (int kt = kt0; kt <= q0 + 127; kt += 32) {
        __syncthreads();
        {
            const float* Kb = g_kn  + (size_t)(b * TSEQ + kt) * KVC + kvh * HD;
            const float* Vb = g_qkv + (size_t)(b * TSEQ + kt) * 4096 + 3072 + kvh * HD;
#pragma unroll
            for (int i = 0; i < 4; i++) {
                const int f   = i * 256 + tid;
                const int r   = f >> 5;
                const int c4  = f & 31;
                const int dst = r * KROW + (c4 >> 2) * 20 + (c4 & 3) * 4;
                *(float4*)(Ksm + dst) = *(const float4*)(Kb + (size_t)r * KVC  + c4 * 4);
                *(float4*)(Vsm + dst) = *(const float4*)(Vb + (size_t)r * 4096 + c4 * 4);
            }
        }
        __syncthreads();

        if (kt > wq_hi || kt + 31 < wq_lo - WS) continue;

#pragma unroll 1
        for (int j0 = 0; j0 < 32; j0 += 4) {
            float sv[4][4];
#pragma unroll
            for (int jj = 0; jj < 4; jj++) {
                const float4* kr4 = (const float4*)(Ksm + (j0 + jj) * KROW + oct * 20);
                float4 k0 = kr4[0], k1 = kr4[1], k2 = kr4[2], k3 = kr4[3];
                const uint64_t kp0 = pk2(k0.x, k0.y), kp1 = pk2(k0.z, k0.w);
                const uint64_t kp2 = pk2(k1.x, k1.y), kp3 = pk2(k1.z, k1.w);
                const uint64_t kp4 = pk2(k2.x, k2.y), kp5 = pk2(k2.z, k2.w);
                const uint64_t kp6 = pk2(k3.x, k3.y), kp7 = pk2(k3.z, k3.w);
#pragma unroll
                for (int r = 0; r < 4; r++) {
                    uint64_t d0 = 0ull, d1 = 0ull;
                    d0 = fma2(q2[r][0], kp0, d0);
                    d1 = fma2(q2[r][1], kp1, d1);
                    d0 = fma2(q2[r][2], kp2, d0);
                    d1 = fma2(q2[r][3], kp3, d1);
                    d0 = fma2(q2[r][4], kp4, d0);
                    d1 = fma2(q2[r][5], kp5, d1);
                    d0 = fma2(q2[r][6], kp6, d0);
                    d1 = fma2(q2[r][7], kp7, d1);
                    float2 e0 = upk2(d0), e1 = upk2(d1);
                    sv[jj][r] = (e0.x + e0.y) + (e1.x + e1.y);
                }
            }
#pragma unroll
            for (int jj = 0; jj < 4; jj++)
#pragma unroll
                for (int r = 0; r < 4; r++)
                    sv[jj][r] += __shfl_xor_sync(0xffffffffu, sv[jj][r], 1);
#pragma unroll
            for (int jj = 0; jj < 4; jj++)
#pragma unroll
                for (int r = 0; r < 4; r++)
                    sv[jj][r] += __shfl_xor_sync(0xffffffffu, sv[jj][r], 2);
#pragma unroll
            for (int jj = 0; jj < 4; jj++)
#pragma unroll
                for (int r = 0; r < 4; r++)
                    sv[jj][r] += __shfl_xor_sync(0xffffffffu, sv[jj][r], 4);

            float pv[4][4];
#pragma unroll
            for (int jj = 0; jj < 4; jj++)
#pragma unroll
                for (int r = 0; r < 4; r++) {
                    const int kj = kt + j0 + jj;
                    const bool valid = (kj <= qi[r]) && (kj >= qi[r] - WS);
                    const float e = ex2f(sv[jj][r] - M2);
                    pv[jj][r] = valid ? e : 0.f;
                    lsum[r] += pv[jj][r];
                }

#pragma unroll
            for (int jj = 0; jj < 4; jj++) {
                const float4* vr4 = (const float4*)(Vsm + (j0 + jj) * KROW + oct * 20);
                float4 v0 = vr4[0], v1 = vr4[1], v2 = vr4[2], v3 = vr4[3];
                const uint64_t vp0 = pk2(v0.x, v0.y), vp1 = pk2(v0.z, v0.w);
                const uint64_t vp2 = pk2(v1.x, v1.y), vp3 = pk2(v1.z, v1.w);
                const uint64_t vp4 = pk2(v2.x, v2.y), vp5 = pk2(v2.z, v2.w);
                const uint64_t vp6 = pk2(v3.x, v3.y), vp7 = pk2(v3.z, v3.w);
#pragma unroll
                for (int r = 0; r < 4; r++) {
                    const uint64_t pp = pk2(pv[jj][r], pv[jj][r]);
                    acc[r][0] = fma2(pp, vp0, acc[r][0]);
                    acc[r][1] = fma2(pp, vp1, acc[r][1]);
                    acc[r][2] = fma2(pp, vp2, acc[r][2]);
                    acc[r][3] = fma2(pp, vp3, acc[r][3]);
                    acc[r][4] = fma2(pp, vp4, acc[r][4]);
                    acc[r][5] = fma2(pp, vp5, acc[r][5]);
                    acc[r][6] = fma2(pp, vp6, acc[r][6]);
                    acc[r][7] = fma2(pp, vp7, acc[r][7]);
                }
            }
        }
    }

#pragma unroll
    for (int r = 0; r < 4; r++) {
        const float ag  = g_ag[(size_t)(b * TSEQ + qi[r]) * NH + h];
        const float inv = ag / lsum[r];
        __nv_bfloat16* base = g_y2 + (size_t)(b * TSEQ + qi[r]) * 4096 + h * HD + oct * 16;
#pragma unroll
        for (int i = 0; i < 8; i++) {
            float2 a = upk2(acc[r][i]);
            const float f0 = a.x * inv, f1 = a.y * inv;
            __nv_bfloat16 h0 = __float2bfloat16(f0);
            __nv_bfloat16 h1 = __float2bfloat16(f1);
            __nv_bfloat16 l0 = __float2bfloat16(f0 - __bfloat162float(h0));
            __nv_bfloat16 l1 = __float2bfloat16(f1 - __bfloat162float(h1));
            *(__nv_bfloat162*)(base + 2 * i)        = __nv_bfloat162(h0, h1);
            *(__nv_bfloat162*)(base + 2048 + 2 * i) = __nv_bfloat162(l0, l1);
        }
    }
}

// ---------------- launcher ---------------------------------------------------
extern "C" void kernel_launch(void* const* d_in, const int* in_sizes, int n_in,
                              void* d_out, int out_size)
{
    const float* x     = (const float*)d_in[0];
    const float* ve    = (const float*)d_in[1];
    const float* cosb  = (const float*)d_in[2];
    const float* sinb  = (const float*)d_in[3];
    const float* wq    = (const float*)d_in[4];
    const float* wk    = (const float*)d_in[5];
    const float* wv    = (const float*)d_in[6];
    const float* wproj = (const float*)d_in[7];
    const float* wvg   = (const float*)d_in[8];
    const float* wag   = (const float*)d_in[9];
    const float* ps    = (const float*)d_in[10];
    const int*   wsp   = (const int*)  d_in[11];
    float* out = (float*)d_out;

    float *pqkv;
    __nv_bfloat16 *px2, *py2, *pwqkvt, *pwpt;
    cudaGetSymbolAddress((void**)&pqkv,   g_qkv);
    cudaGetSymbolAddress((void**)&px2,    g_x2);
    cudaGetSymbolAddress((void**)&py2,    g_y2);
    cudaGetSymbolAddress((void**)&pwqkvt, g_wqkvt);
    cudaGetSymbolAddress((void**)&pwpt,   g_wpt);

    cudaFuncSetAttribute(mma_gemm, cudaFuncAttributeMaxDynamicSharedMemorySize, GSMEM_TOT);

    // 1: all operand conversions in one launch
    conv_all<<<20480, 256>>>(x, wq, wk, wv, wproj, px2, pwqkvt, pwpt);
    // 2: fused QKV projection (N=4096)
    mma_gemm<<<dim3(32, MROWS / 128), 256, GSMEM_TOT>>>(px2, pwqkvt, pqkv, 4096, nullptr, 0);
    // 3: fused gates + rope/rmsnorm
    prep_kernel<<<MROWS + MROWS * 24 / 4, 128>>>(x, ve, wvg, wag, cosb, sinb);
    // 4: attention — writes split-bf16 y directly
    attn_kernel<<<dim3(TSEQ / 128, BATCH * NH), 256>>>(wsp);
    // 5: output projection
    mma_gemm<<<dim3(16, MROWS / 128), 256, GSMEM_TOT>>>(py2, pwpt, out, CEMB, ps, 0);
}